// round 1
// baseline (speedup 1.0000x reference)
#include <cuda_runtime.h>
#include <math.h>

// Problem dims (fixed by the reference)
#define Bsz 2
#define Ssz 2048
#define Esz 1024
#define Hsz 16
#define Dsz 64
#define FFsz 4096
#define Msz (Bsz*Ssz)   // 4096 tokens

// ---------------- scratch (device globals; no allocations allowed) ----------
__device__ float g_qkv[(size_t)Msz * 3 * Esz];   // [M, 3E]
__device__ float g_attn[(size_t)Msz * Esz];      // attention output [B,S,E]
__device__ float g_proj[(size_t)Msz * Esz];      // out-proj result
__device__ float g_x1[(size_t)Msz * Esz];        // first LN output (residual src)
__device__ float g_h[(size_t)Msz * FFsz];        // gelu(fc1)
__device__ float g_ff[(size_t)Msz * Esz];        // fc2 result

// ---------------- tiled SGEMM: C[M,N] = A[M,K] * B[N,K]^T + bias -----------
// 128x128 tile, BK=8, 256 threads, 8x8 per thread (split 4+4 fragments).
template<int GELU>
__global__ __launch_bounds__(256)
void gemm_bt_kernel(const float* __restrict__ A, const float* __restrict__ Bm,
                    const float* __restrict__ bias, float* __restrict__ C,
                    int M, int N, int K)
{
    __shared__ float As[8 * 128];
    __shared__ float Bs[8 * 128];

    const int bx = blockIdx.x;   // N tile
    const int by = blockIdx.y;   // M tile
    const int tid = threadIdx.x;
    const int tx = tid & 15;
    const int ty = tid >> 4;

    const int arow = tid >> 1;        // 0..127
    const int acol = (tid & 1) * 4;   // 0 or 4

    const float* Ap = A + (size_t)(by * 128 + arow) * K + acol;
    const float* Bp = Bm + (size_t)(bx * 128 + arow) * K + acol;

    float acc[8][8];
    #pragma unroll
    for (int i = 0; i < 8; i++)
        #pragma unroll
        for (int j = 0; j < 8; j++) acc[i][j] = 0.0f;

    for (int k0 = 0; k0 < K; k0 += 8) {
        const float4 av = *(const float4*)(Ap + k0);
        const float4 bv = *(const float4*)(Bp + k0);
        As[(acol + 0) * 128 + arow] = av.x;
        As[(acol + 1) * 128 + arow] = av.y;
        As[(acol + 2) * 128 + arow] = av.z;
        As[(acol + 3) * 128 + arow] = av.w;
        Bs[(acol + 0) * 128 + arow] = bv.x;
        Bs[(acol + 1) * 128 + arow] = bv.y;
        Bs[(acol + 2) * 128 + arow] = bv.z;
        Bs[(acol + 3) * 128 + arow] = bv.w;
        __syncthreads();

        #pragma unroll
        for (int k = 0; k < 8; k++) {
            const float4 a0 = *(const float4*)&As[k * 128 + 4 * ty];
            const float4 a1 = *(const float4*)&As[k * 128 + 64 + 4 * ty];
            const float4 b0 = *(const float4*)&Bs[k * 128 + 4 * tx];
            const float4 b1 = *(const float4*)&Bs[k * 128 + 64 + 4 * tx];
            const float ar[8] = {a0.x, a0.y, a0.z, a0.w, a1.x, a1.y, a1.z, a1.w};
            const float br[8] = {b0.x, b0.y, b0.z, b0.w, b1.x, b1.y, b1.z, b1.w};
            #pragma unroll
            for (int i = 0; i < 8; i++)
                #pragma unroll
                for (int j = 0; j < 8; j++)
                    acc[i][j] += ar[i] * br[j];
        }
        __syncthreads();
    }

    // epilogue
    const float4 bi0 = *(const float4*)&bias[bx * 128 + 4 * tx];
    const float4 bi1 = *(const float4*)&bias[bx * 128 + 64 + 4 * tx];
    const float bb[8] = {bi0.x, bi0.y, bi0.z, bi0.w, bi1.x, bi1.y, bi1.z, bi1.w};

    #pragma unroll
    for (int i = 0; i < 8; i++) {
        const int rloc = (i < 4) ? (4 * ty + i) : (64 + 4 * ty + (i - 4));
        float* Crow = C + (size_t)(by * 128 + rloc) * N + bx * 128;
        float v[8];
        #pragma unroll
        for (int j = 0; j < 8; j++) {
            float t = acc[i][j] + bb[j];
            if (GELU) t = 0.5f * t * (1.0f + erff(t * 0.70710678118654752f));
            v[j] = t;
        }
        float4 o0 = make_float4(v[0], v[1], v[2], v[3]);
        float4 o1 = make_float4(v[4], v[5], v[6], v[7]);
        *(float4*)(Crow + 4 * tx) = o0;
        *(float4*)(Crow + 64 + 4 * tx) = o1;
    }
}

// ---------------- flash attention -------------------------------------------
// grid (S/64, H, B), 256 threads. Q tile 64x64 resident; KV tiles 64 rows.
#define FA_STRIDE 68
#define FA_SMEM (4 * 64 * FA_STRIDE * 4)

__global__ __launch_bounds__(256)
void flash_kernel(const float* __restrict__ qkv, float* __restrict__ outp)
{
    extern __shared__ float sm[];
    float* Qt = sm;                       // Qt[d][i]  (transposed)
    float* Kt = sm + 64 * FA_STRIDE;      // Kt[d][j]  (transposed)
    float* Vs = sm + 2 * 64 * FA_STRIDE;  // Vs[j][d]  (natural)
    float* Ps = sm + 3 * 64 * FA_STRIDE;  // Ps[i][j]

    const int qb = blockIdx.x, h = blockIdx.y, b = blockIdx.z;
    const int tid = threadIdx.x;
    const int tx = tid & 15, ty = tid >> 4;
    const float scale = 0.125f;  // 1/sqrt(64)

    const size_t base = (size_t)b * Ssz * (3 * Esz);
    const float* qbase = qkv + base + h * Dsz;
    const float* kbase = qkv + base + Esz + h * Dsz;
    const float* vbase = qkv + base + 2 * Esz + h * Dsz;

    // load Q tile (transposed into smem)
    #pragma unroll
    for (int it = 0; it < 4; it++) {
        const int idx = tid + it * 256;
        const int r = idx >> 4;
        const int c4 = (idx & 15) << 2;
        const float4 qv = *(const float4*)(qbase + (size_t)(qb * 64 + r) * (3 * Esz) + c4);
        Qt[(c4 + 0) * FA_STRIDE + r] = qv.x;
        Qt[(c4 + 1) * FA_STRIDE + r] = qv.y;
        Qt[(c4 + 2) * FA_STRIDE + r] = qv.z;
        Qt[(c4 + 3) * FA_STRIDE + r] = qv.w;
    }

    float o[4][4] = {};
    float mrow[4] = {-INFINITY, -INFINITY, -INFINITY, -INFINITY};
    float lrow[4] = {};

    for (int kb = 0; kb < Ssz / 64; kb++) {
        __syncthreads();  // previous PV done (also orders Q load on iter 0)
        #pragma unroll
        for (int it = 0; it < 4; it++) {
            const int idx = tid + it * 256;
            const int r = idx >> 4;
            const int c4 = (idx & 15) << 2;
            const size_t rowoff = (size_t)(kb * 64 + r) * (3 * Esz) + c4;
            const float4 kv = *(const float4*)(kbase + rowoff);
            Kt[(c4 + 0) * FA_STRIDE + r] = kv.x;
            Kt[(c4 + 1) * FA_STRIDE + r] = kv.y;
            Kt[(c4 + 2) * FA_STRIDE + r] = kv.z;
            Kt[(c4 + 3) * FA_STRIDE + r] = kv.w;
            const float4 vv = *(const float4*)(vbase + rowoff);
            *(float4*)&Vs[r * FA_STRIDE + c4] = vv;
        }
        __syncthreads();

        // S = Q K^T (64x64x64), 4x4 per thread
        float s[4][4] = {};
        #pragma unroll 8
        for (int d = 0; d < 64; d++) {
            const float4 qv = *(const float4*)&Qt[d * FA_STRIDE + 4 * ty];
            const float4 kv = *(const float4*)&Kt[d * FA_STRIDE + 4 * tx];
            const float qa[4] = {qv.x, qv.y, qv.z, qv.w};
            const float ka[4] = {kv.x, kv.y, kv.z, kv.w};
            #pragma unroll
            for (int i = 0; i < 4; i++)
                #pragma unroll
                for (int j = 0; j < 4; j++)
                    s[i][j] += qa[i] * ka[j];
        }

        // online softmax per row (row owners = 16 lanes in a half-warp)
        #pragma unroll
        for (int i = 0; i < 4; i++) {
            float rm = -INFINITY;
            #pragma unroll
            for (int j = 0; j < 4; j++) { s[i][j] *= scale; rm = fmaxf(rm, s[i][j]); }
            #pragma unroll
            for (int ofs = 1; ofs < 16; ofs <<= 1)
                rm = fmaxf(rm, __shfl_xor_sync(0xffffffffu, rm, ofs));
            const float mn = fmaxf(mrow[i], rm);
            const float corr = __expf(mrow[i] - mn);
            mrow[i] = mn;
            float rs = 0.0f;
            #pragma unroll
            for (int j = 0; j < 4; j++) { s[i][j] = __expf(s[i][j] - mn); rs += s[i][j]; }
            #pragma unroll
            for (int ofs = 1; ofs < 16; ofs <<= 1)
                rs += __shfl_xor_sync(0xffffffffu, rs, ofs);
            lrow[i] = lrow[i] * corr + rs;
            #pragma unroll
            for (int j = 0; j < 4; j++) o[i][j] *= corr;
            #pragma unroll
            for (int j = 0; j < 4; j++)
                Ps[(4 * ty + i) * FA_STRIDE + 4 * tx + j] = s[i][j];
        }
        __syncthreads();

        // O += P V   (64x64x64)
        #pragma unroll 4
        for (int jj0 = 0; jj0 < 64; jj0 += 4) {
            float p_[4][4];
            #pragma unroll
            for (int i = 0; i < 4; i++) {
                const float4 pv = *(const float4*)&Ps[(4 * ty + i) * FA_STRIDE + jj0];
                p_[i][0] = pv.x; p_[i][1] = pv.y; p_[i][2] = pv.z; p_[i][3] = pv.w;
            }
            #pragma unroll
            for (int u = 0; u < 4; u++) {
                const float4 vv = *(const float4*)&Vs[(jj0 + u) * FA_STRIDE + 4 * tx];
                const float va[4] = {vv.x, vv.y, vv.z, vv.w};
                #pragma unroll
                for (int i = 0; i < 4; i++)
                    #pragma unroll
                    for (int j = 0; j < 4; j++)
                        o[i][j] += p_[i][u] * va[j];
            }
        }
    }

    // write out[b, q, h*64 + d]  ([B,S,E] layout)
    #pragma unroll
    for (int i = 0; i < 4; i++) {
        const float inv = 1.0f / lrow[i];
        float4 ov = make_float4(o[i][0] * inv, o[i][1] * inv, o[i][2] * inv, o[i][3] * inv);
        *(float4*)(outp + ((size_t)b * Ssz + qb * 64 + 4 * ty + i) * Esz + h * Dsz + 4 * tx) = ov;
    }
}

// ---------------- fused residual-add + LayerNorm ----------------------------
__global__ __launch_bounds__(256)
void add_ln_kernel(const float* __restrict__ A, const float* __restrict__ Bv,
                   const float* __restrict__ g, const float* __restrict__ be,
                   float* __restrict__ Y)
{
    const int row = blockIdx.x;
    const int tid = threadIdx.x;
    const float4 av = ((const float4*)(A + (size_t)row * Esz))[tid];
    const float4 bv = ((const float4*)(Bv + (size_t)row * Esz))[tid];
    const float v0 = av.x + bv.x, v1 = av.y + bv.y, v2 = av.z + bv.z, v3 = av.w + bv.w;

    float s = v0 + v1 + v2 + v3;
    float s2 = v0 * v0 + v1 * v1 + v2 * v2 + v3 * v3;
    #pragma unroll
    for (int o = 16; o; o >>= 1) {
        s += __shfl_xor_sync(0xffffffffu, s, o);
        s2 += __shfl_xor_sync(0xffffffffu, s2, o);
    }
    __shared__ float ss[8], ss2[8];
    const int w = tid >> 5, ln = tid & 31;
    if (ln == 0) { ss[w] = s; ss2[w] = s2; }
    __syncthreads();
    if (tid < 8) {
        s = ss[tid]; s2 = ss2[tid];
        #pragma unroll
        for (int o = 4; o; o >>= 1) {
            s += __shfl_xor_sync(0x000000ffu, s, o);
            s2 += __shfl_xor_sync(0x000000ffu, s2, o);
        }
        if (tid == 0) { ss[0] = s; ss2[0] = s2; }
    }
    __syncthreads();
    const float mean = ss[0] * (1.0f / Esz);
    const float var = ss2[0] * (1.0f / Esz) - mean * mean;
    const float rstd = rsqrtf(var + 1e-5f);

    const float4 gv = ((const float4*)g)[tid];
    const float4 bev = ((const float4*)be)[tid];
    float4 o4;
    o4.x = (v0 - mean) * rstd * gv.x + bev.x;
    o4.y = (v1 - mean) * rstd * gv.y + bev.y;
    o4.z = (v2 - mean) * rstd * gv.z + bev.z;
    o4.w = (v3 - mean) * rstd * gv.w + bev.w;
    ((float4*)(Y + (size_t)row * Esz))[tid] = o4;
}

// ---------------- launch -----------------------------------------------------
extern "C" void kernel_launch(void* const* d_in, const int* in_sizes, int n_in,
                              void* d_out, int out_size)
{
    (void)in_sizes; (void)n_in; (void)out_size;
    const float* x     = (const float*)d_in[0];
    const float* w_qkv = (const float*)d_in[1];
    const float* b_qkv = (const float*)d_in[2];
    const float* w_out = (const float*)d_in[3];
    const float* b_out = (const float*)d_in[4];
    const float* g1    = (const float*)d_in[5];
    const float* beta1 = (const float*)d_in[6];
    const float* w_fc1 = (const float*)d_in[7];
    const float* b_fc1 = (const float*)d_in[8];
    const float* w_fc2 = (const float*)d_in[9];
    const float* b_fc2 = (const float*)d_in[10];
    const float* g2    = (const float*)d_in[11];
    const float* beta2 = (const float*)d_in[12];

    float *qkv, *attn, *proj, *x1, *hbuf, *ff;
    cudaGetSymbolAddress((void**)&qkv,  g_qkv);
    cudaGetSymbolAddress((void**)&attn, g_attn);
    cudaGetSymbolAddress((void**)&proj, g_proj);
    cudaGetSymbolAddress((void**)&x1,   g_x1);
    cudaGetSymbolAddress((void**)&hbuf, g_h);
    cudaGetSymbolAddress((void**)&ff,   g_ff);

    cudaFuncSetAttribute(flash_kernel, cudaFuncAttributeMaxDynamicSharedMemorySize, FA_SMEM);

    // 1) qkv = x @ w_qkv^T + b_qkv           [4096, 3072]
    gemm_bt_kernel<0><<<dim3(3 * Esz / 128, Msz / 128), 256>>>(x, w_qkv, b_qkv, qkv, Msz, 3 * Esz, Esz);
    // 2) attention (flash, per 64-row q tile per head per batch)
    flash_kernel<<<dim3(Ssz / 64, Hsz, Bsz), 256, FA_SMEM>>>(qkv, attn);
    // 3) proj = attn @ w_out^T + b_out
    gemm_bt_kernel<0><<<dim3(Esz / 128, Msz / 128), 256>>>(attn, w_out, b_out, proj, Msz, Esz, Esz);
    // 4) x1 = LN(x + proj)
    add_ln_kernel<<<Msz, 256>>>(x, proj, g1, beta1, x1);
    // 5) h = gelu(x1 @ w_fc1^T + b_fc1)       [4096, 4096]
    gemm_bt_kernel<1><<<dim3(FFsz / 128, Msz / 128), 256>>>(x1, w_fc1, b_fc1, hbuf, Msz, FFsz, Esz);
    // 6) ff = h @ w_fc2^T + b_fc2             [4096, 1024]
    gemm_bt_kernel<0><<<dim3(Esz / 128, Msz / 128), 256>>>(hbuf, w_fc2, b_fc2, ff, Msz, Esz, FFsz);
    // 7) out = LN(x1 + ff)
    add_ln_kernel<<<Msz, 256>>>(x1, ff, g2, beta2, (float*)d_out);
}

// round 3
// speedup vs baseline: 1.8918x; 1.8918x over previous
#include <cuda_runtime.h>
#include <cuda_bf16.h>
#include <math.h>
#include <stdint.h>

// Problem dims (fixed by the reference)
#define Bsz 2
#define Ssz 2048
#define Esz 1024
#define Hsz 16
#define Dsz 64
#define FFsz 4096
#define Msz (Bsz*Ssz)   // 4096 tokens

// ===================== helpers ===============================================
__device__ __forceinline__ uint32_t smem_to_u32(const void* p) {
    uint32_t a;
    asm("{ .reg .u64 t; cvta.to.shared.u64 t, %1; cvt.u32.u64 %0, t; }" : "=r"(a) : "l"(p));
    return a;
}
#define CPASYNC16(saddr, gptr) \
    asm volatile("cp.async.cg.shared.global [%0], [%1], 16;" :: "r"((uint32_t)(saddr)), "l"(gptr))
#define CPASYNC_COMMIT() asm volatile("cp.async.commit_group;" ::: "memory")
#define CPASYNC_WAIT2() asm volatile("cp.async.wait_group 2;" ::: "memory")
#define CPASYNC_WAIT0() asm volatile("cp.async.wait_group 0;" ::: "memory")

__device__ __forceinline__ void ldmatrix_x4(uint32_t& r0, uint32_t& r1, uint32_t& r2, uint32_t& r3,
                                            uint32_t addr) {
    asm volatile("ldmatrix.sync.aligned.m8n8.x4.shared.b16 {%0,%1,%2,%3}, [%4];"
        : "=r"(r0), "=r"(r1), "=r"(r2), "=r"(r3) : "r"(addr));
}
__device__ __forceinline__ void mma16816(float* d, const uint32_t* a, const uint32_t* b) {
    asm volatile("mma.sync.aligned.m16n8k16.row.col.f32.bf16.bf16.f32 "
        "{%0,%1,%2,%3}, {%4,%5,%6,%7}, {%8,%9}, {%0,%1,%2,%3};"
        : "+f"(d[0]), "+f"(d[1]), "+f"(d[2]), "+f"(d[3])
        : "r"(a[0]), "r"(a[1]), "r"(a[2]), "r"(a[3]), "r"(b[0]), "r"(b[1]));
}

// ===================== scratch (device globals) ==============================
__device__ float g_qkv[(size_t)Msz * 3 * Esz];
__device__ float g_attn[(size_t)Msz * Esz];
__device__ float g_proj[(size_t)Msz * Esz];
__device__ float g_x1[(size_t)Msz * Esz];
__device__ float g_h[(size_t)Msz * FFsz];
__device__ float g_ff[(size_t)Msz * Esz];
// bf16x3 operands
__device__ __nv_bfloat16 g_x3[(size_t)Msz * 3 * Esz];
__device__ __nv_bfloat16 g_attn3[(size_t)Msz * 3 * Esz];
__device__ __nv_bfloat16 g_x13[(size_t)Msz * 3 * Esz];
__device__ __nv_bfloat16 g_h3[(size_t)Msz * 3 * FFsz];
__device__ __nv_bfloat16 g_wqkv3[(size_t)(3 * Esz) * 3 * Esz];
__device__ __nv_bfloat16 g_wout3[(size_t)Esz * 3 * Esz];
__device__ __nv_bfloat16 g_wfc13[(size_t)FFsz * 3 * Esz];
__device__ __nv_bfloat16 g_wfc23[(size_t)Esz * 3 * FFsz];

// ===================== bf16x3 split ==========================================
// ATYPE=1 -> [hi | lo | hi]  (A-side), ATYPE=0 -> [hi | hi | lo]  (B-side)
template<int ATYPE>
__global__ __launch_bounds__(256)
void split3_kernel(const float* __restrict__ src, __nv_bfloat16* __restrict__ dst, int K)
{
    const int row = blockIdx.x;
    const float* s = src + (size_t)row * K;
    __nv_bfloat16* d = dst + (size_t)row * 3 * K;
    for (int k = threadIdx.x; k < K; k += 256) {
        const float x = s[k];
        const __nv_bfloat16 h = __float2bfloat16(x);
        const __nv_bfloat16 l = __float2bfloat16(x - __bfloat162float(h));
        if (ATYPE) { d[k] = h; d[K + k] = l; d[2 * K + k] = h; }
        else       { d[k] = h; d[K + k] = h; d[2 * K + k] = l; }
    }
}

// ===================== HMMA bf16 GEMM ========================================
// C[Msz,N] = A[Msz,K3]*B[N,K3]^T + bias (+GELU).
// 128x128 CTA tile, 256 threads (8 warps, 4x2 warp grid, warp tile 32x64),
// K-chunk 64 elems (128B rows, SW128 swizzle), 3-stage cp.async pipeline.
#define NBUF 3
#define STAGE_BYTES (128 * 128)
#define GEMM_SMEM (NBUF * 2 * STAGE_BYTES)

template<int GELU>
__global__ __launch_bounds__(256)
void gemm_mma_kernel(const __nv_bfloat16* __restrict__ A, const __nv_bfloat16* __restrict__ Bm,
                     const float* __restrict__ bias, float* __restrict__ C,
                     int N, int K3)
{
    extern __shared__ __align__(1024) char smem[];
    const uint32_t sbase = smem_to_u32(smem);
    const int tid = threadIdx.x;
    const int lane = tid & 31;
    const int wid = tid >> 5;
    const int wm = wid & 3;        // warp row (32 rows each)
    const int wn = wid >> 2;       // warp col (64 cols each)
    const int bx = blockIdx.x, by = blockIdx.y;

    // ---- cp.async thread pattern: 4 chunks of 16B per operand per stage ----
    // chunk t: idx = tid + t*256; smem row = idx>>3; 16B-col = idx&7
    uint32_t st_off[4];
    #pragma unroll
    for (int t = 0; t < 4; t++) {
        const int idx = tid + t * 256;
        const int row = idx >> 3;
        const int c = (idx & 7) * 16;
        st_off[t] = (uint32_t)(row * 128 + (c ^ ((row & 7) * 16)));
    }
    const size_t ldb = (size_t)K3 * 2;  // row stride in bytes
    const char* Agp[4];
    const char* Bgp[4];
    #pragma unroll
    for (int t = 0; t < 4; t++) {
        const int idx = tid + t * 256;
        Agp[t] = (const char*)A + (size_t)(by * 128 + (idx >> 3)) * ldb + (idx & 7) * 16;
        Bgp[t] = (const char*)Bm + (size_t)(bx * 128 + (idx >> 3)) * ldb + (idx & 7) * 16;
    }

    // ---- ldmatrix address precompute (SW128: sw(x)=row*128 + (c ^ (row&7)*16)) ----
    const uint32_t colxor = (uint32_t)((lane & 7) * 16);
    // A: lane -> row = wm*32 + i*16 + (lane&15), part = (lane>>4)*16
    const uint32_t a_rowbase = (uint32_t)((wm * 32 + (lane & 15)) * 128);
    const uint32_t a_part = (uint32_t)((lane >> 4) * 16);
    // B: lane -> row = wn*64 + jp*16 + ((lane>>4)<<3) + (lane&7), part = ((lane>>3)&1)*16
    const uint32_t b_rowbase = (uint32_t)((wn * 64 + ((lane >> 4) << 3) + (lane & 7)) * 128);
    const uint32_t b_part = (uint32_t)(((lane >> 3) & 1) * 16);

    float acc[2][8][4];
    #pragma unroll
    for (int i = 0; i < 2; i++)
        #pragma unroll
        for (int j = 0; j < 8; j++)
            #pragma unroll
            for (int u = 0; u < 4; u++) acc[i][j][u] = 0.0f;

    const int S = K3 / 64;

    // prefetch 3 stages
    #pragma unroll
    for (int p = 0; p < NBUF; p++) {
        const uint32_t ab = sbase + p * 2 * STAGE_BYTES;
        const uint32_t bb = ab + STAGE_BYTES;
        #pragma unroll
        for (int t = 0; t < 4; t++) {
            CPASYNC16(ab + st_off[t], Agp[t] + (size_t)p * 128);
            CPASYNC16(bb + st_off[t], Bgp[t] + (size_t)p * 128);
        }
        CPASYNC_COMMIT();
    }

    #pragma unroll 1
    for (int s = 0; s < S; s++) {
        CPASYNC_WAIT2();
        __syncthreads();
        const uint32_t ab = sbase + (s % NBUF) * 2 * STAGE_BYTES;
        const uint32_t bb = ab + STAGE_BYTES;

        #pragma unroll
        for (int k = 0; k < 4; k++) {
            const uint32_t kb = (uint32_t)(k * 32);
            uint32_t a[2][4], b[8][2];
            #pragma unroll
            for (int i = 0; i < 2; i++)
                ldmatrix_x4(a[i][0], a[i][1], a[i][2], a[i][3],
                            ab + a_rowbase + (uint32_t)(i * 2048) + ((kb + a_part) ^ colxor));
            #pragma unroll
            for (int jp = 0; jp < 4; jp++) {
                uint32_t r0, r1, r2, r3;
                ldmatrix_x4(r0, r1, r2, r3,
                            bb + b_rowbase + (uint32_t)(jp * 2048) + ((kb + b_part) ^ colxor));
                b[2 * jp][0] = r0; b[2 * jp][1] = r1;
                b[2 * jp + 1][0] = r2; b[2 * jp + 1][1] = r3;
            }
            #pragma unroll
            for (int i = 0; i < 2; i++)
                #pragma unroll
                for (int j = 0; j < 8; j++)
                    mma16816(acc[i][j], a[i], b[j]);
        }
        __syncthreads();
        if (s + NBUF < S) {
            const int sn = s + NBUF;
            #pragma unroll
            for (int t = 0; t < 4; t++) {
                CPASYNC16(ab + st_off[t], Agp[t] + (size_t)sn * 128);
                CPASYNC16(bb + st_off[t], Bgp[t] + (size_t)sn * 128);
            }
            CPASYNC_COMMIT();
        }
    }

    // ---- epilogue: registers -> global, with bias (+GELU) ----
    const int row0 = by * 128 + wm * 32 + (lane >> 2);
    const int col0 = bx * 128 + wn * 64 + (lane & 3) * 2;
    #pragma unroll
    for (int j = 0; j < 8; j++) {
        const int col = col0 + j * 8;
        const float2 bv = *(const float2*)&bias[col];
        #pragma unroll
        for (int i = 0; i < 2; i++) {
            #pragma unroll
            for (int half = 0; half < 2; half++) {
                const int row = row0 + i * 16 + half * 8;
                float v0 = acc[i][j][half * 2 + 0] + bv.x;
                float v1 = acc[i][j][half * 2 + 1] + bv.y;
                if (GELU) {
                    v0 = 0.5f * v0 * (1.0f + erff(v0 * 0.70710678118654752f));
                    v1 = 0.5f * v1 * (1.0f + erff(v1 * 0.70710678118654752f));
                }
                *(float2*)(C + (size_t)row * N + col) = make_float2(v0, v1);
            }
        }
    }
}

// ===================== flash attention (fp32 SIMT) ===========================
#define FA_STRIDE 68
#define FA_SMEM (4 * 64 * FA_STRIDE * 4)

__global__ __launch_bounds__(256)
void flash_kernel(const float* __restrict__ qkv, float* __restrict__ outp)
{
    extern __shared__ float sm[];
    float* Qt = sm;
    float* Kt = sm + 64 * FA_STRIDE;
    float* Vs = sm + 2 * 64 * FA_STRIDE;
    float* Ps = sm + 3 * 64 * FA_STRIDE;

    const int qb = blockIdx.x, h = blockIdx.y, b = blockIdx.z;
    const int tid = threadIdx.x;
    const int tx = tid & 15, ty = tid >> 4;
    const float scale = 0.125f;

    const size_t base = (size_t)b * Ssz * (3 * Esz);
    const float* qbase = qkv + base + h * Dsz;
    const float* kbase = qkv + base + Esz + h * Dsz;
    const float* vbase = qkv + base + 2 * Esz + h * Dsz;

    #pragma unroll
    for (int it = 0; it < 4; it++) {
        const int idx = tid + it * 256;
        const int r = idx >> 4;
        const int c4 = (idx & 15) << 2;
        const float4 qv = *(const float4*)(qbase + (size_t)(qb * 64 + r) * (3 * Esz) + c4);
        Qt[(c4 + 0) * FA_STRIDE + r] = qv.x;
        Qt[(c4 + 1) * FA_STRIDE + r] = qv.y;
        Qt[(c4 + 2) * FA_STRIDE + r] = qv.z;
        Qt[(c4 + 3) * FA_STRIDE + r] = qv.w;
    }

    float o[4][4] = {};
    float mrow[4] = {-INFINITY, -INFINITY, -INFINITY, -INFINITY};
    float lrow[4] = {};

    for (int kb = 0; kb < Ssz / 64; kb++) {
        __syncthreads();
        #pragma unroll
        for (int it = 0; it < 4; it++) {
            const int idx = tid + it * 256;
            const int r = idx >> 4;
            const int c4 = (idx & 15) << 2;
            const size_t rowoff = (size_t)(kb * 64 + r) * (3 * Esz) + c4;
            const float4 kv = *(const float4*)(kbase + rowoff);
            Kt[(c4 + 0) * FA_STRIDE + r] = kv.x;
            Kt[(c4 + 1) * FA_STRIDE + r] = kv.y;
            Kt[(c4 + 2) * FA_STRIDE + r] = kv.z;
            Kt[(c4 + 3) * FA_STRIDE + r] = kv.w;
            const float4 vv = *(const float4*)(vbase + rowoff);
            *(float4*)&Vs[r * FA_STRIDE + c4] = vv;
        }
        __syncthreads();

        float s[4][4] = {};
        #pragma unroll 8
        for (int d = 0; d < 64; d++) {
            const float4 qv = *(const float4*)&Qt[d * FA_STRIDE + 4 * ty];
            const float4 kv = *(const float4*)&Kt[d * FA_STRIDE + 4 * tx];
            const float qa[4] = {qv.x, qv.y, qv.z, qv.w};
            const float ka[4] = {kv.x, kv.y, kv.z, kv.w};
            #pragma unroll
            for (int i = 0; i < 4; i++)
                #pragma unroll
                for (int j = 0; j < 4; j++)
                    s[i][j] += qa[i] * ka[j];
        }

        #pragma unroll
        for (int i = 0; i < 4; i++) {
            float rm = -INFINITY;
            #pragma unroll
            for (int j = 0; j < 4; j++) { s[i][j] *= scale; rm = fmaxf(rm, s[i][j]); }
            #pragma unroll
            for (int ofs = 1; ofs < 16; ofs <<= 1)
                rm = fmaxf(rm, __shfl_xor_sync(0xffffffffu, rm, ofs));
            const float mn = fmaxf(mrow[i], rm);
            const float corr = __expf(mrow[i] - mn);
            mrow[i] = mn;
            float rs = 0.0f;
            #pragma unroll
            for (int j = 0; j < 4; j++) { s[i][j] = __expf(s[i][j] - mn); rs += s[i][j]; }
            #pragma unroll
            for (int ofs = 1; ofs < 16; ofs <<= 1)
                rs += __shfl_xor_sync(0xffffffffu, rs, ofs);
            lrow[i] = lrow[i] * corr + rs;
            #pragma unroll
            for (int j = 0; j < 4; j++) o[i][j] *= corr;
            #pragma unroll
            for (int j = 0; j < 4; j++)
                Ps[(4 * ty + i) * FA_STRIDE + 4 * tx + j] = s[i][j];
        }
        __syncthreads();

        #pragma unroll 4
        for (int jj0 = 0; jj0 < 64; jj0 += 4) {
            float p_[4][4];
            #pragma unroll
            for (int i = 0; i < 4; i++) {
                const float4 pv = *(const float4*)&Ps[(4 * ty + i) * FA_STRIDE + jj0];
                p_[i][0] = pv.x; p_[i][1] = pv.y; p_[i][2] = pv.z; p_[i][3] = pv.w;
            }
            #pragma unroll
            for (int u = 0; u < 4; u++) {
                const float4 vv = *(const float4*)&Vs[(jj0 + u) * FA_STRIDE + 4 * tx];
                const float va[4] = {vv.x, vv.y, vv.z, vv.w};
                #pragma unroll
                for (int i = 0; i < 4; i++)
                    #pragma unroll
                    for (int j = 0; j < 4; j++)
                        o[i][j] += p_[i][u] * va[j];
            }
        }
    }

    #pragma unroll
    for (int i = 0; i < 4; i++) {
        const float inv = 1.0f / lrow[i];
        float4 ov = make_float4(o[i][0] * inv, o[i][1] * inv, o[i][2] * inv, o[i][3] * inv);
        *(float4*)(outp + ((size_t)b * Ssz + qb * 64 + 4 * ty + i) * Esz + h * Dsz + 4 * tx) = ov;
    }
}

// ===================== fused residual-add + LayerNorm ========================
__global__ __launch_bounds__(256)
void add_ln_kernel(const float* __restrict__ A, const float* __restrict__ Bv,
                   const float* __restrict__ g, const float* __restrict__ be,
                   float* __restrict__ Y)
{
    const int row = blockIdx.x;
    const int tid = threadIdx.x;
    const float4 av = ((const float4*)(A + (size_t)row * Esz))[tid];
    const float4 bv = ((const float4*)(Bv + (size_t)row * Esz))[tid];
    const float v0 = av.x + bv.x, v1 = av.y + bv.y, v2 = av.z + bv.z, v3 = av.w + bv.w;

    float s = v0 + v1 + v2 + v3;
    float s2 = v0 * v0 + v1 * v1 + v2 * v2 + v3 * v3;
    #pragma unroll
    for (int o = 16; o; o >>= 1) {
        s += __shfl_xor_sync(0xffffffffu, s, o);
        s2 += __shfl_xor_sync(0xffffffffu, s2, o);
    }
    __shared__ float ss[8], ss2[8];
    const int w = tid >> 5, ln = tid & 31;
    if (ln == 0) { ss[w] = s; ss2[w] = s2; }
    __syncthreads();
    if (tid < 8) {
        s = ss[tid]; s2 = ss2[tid];
        #pragma unroll
        for (int o = 4; o; o >>= 1) {
            s += __shfl_xor_sync(0x000000ffu, s, o);
            s2 += __shfl_xor_sync(0x000000ffu, s2, o);
        }
        if (tid == 0) { ss[0] = s; ss2[0] = s2; }
    }
    __syncthreads();
    const float mean = ss[0] * (1.0f / Esz);
    const float var = ss2[0] * (1.0f / Esz) - mean * mean;
    const float rstd = rsqrtf(var + 1e-5f);

    const float4 gv = ((const float4*)g)[tid];
    const float4 bev = ((const float4*)be)[tid];
    float4 o4;
    o4.x = (v0 - mean) * rstd * gv.x + bev.x;
    o4.y = (v1 - mean) * rstd * gv.y + bev.y;
    o4.z = (v2 - mean) * rstd * gv.z + bev.z;
    o4.w = (v3 - mean) * rstd * gv.w + bev.w;
    ((float4*)(Y + (size_t)row * Esz))[tid] = o4;
}

// ===================== launch ================================================
extern "C" void kernel_launch(void* const* d_in, const int* in_sizes, int n_in,
                              void* d_out, int out_size)
{
    (void)in_sizes; (void)n_in; (void)out_size;
    const float* x     = (const float*)d_in[0];
    const float* w_qkv = (const float*)d_in[1];
    const float* b_qkv = (const float*)d_in[2];
    const float* w_out = (const float*)d_in[3];
    const float* b_out = (const float*)d_in[4];
    const float* g1    = (const float*)d_in[5];
    const float* beta1 = (const float*)d_in[6];
    const float* w_fc1 = (const float*)d_in[7];
    const float* b_fc1 = (const float*)d_in[8];
    const float* w_fc2 = (const float*)d_in[9];
    const float* b_fc2 = (const float*)d_in[10];
    const float* g2    = (const float*)d_in[11];
    const float* beta2 = (const float*)d_in[12];

    float *qkv, *attn, *proj, *x1, *hbuf, *ff;
    cudaGetSymbolAddress((void**)&qkv,  g_qkv);
    cudaGetSymbolAddress((void**)&attn, g_attn);
    cudaGetSymbolAddress((void**)&proj, g_proj);
    cudaGetSymbolAddress((void**)&x1,   g_x1);
    cudaGetSymbolAddress((void**)&hbuf, g_h);
    cudaGetSymbolAddress((void**)&ff,   g_ff);
    __nv_bfloat16 *x3, *attn3, *x13, *h3, *wq3, *wo3, *w13, *w23;
    cudaGetSymbolAddress((void**)&x3,    g_x3);
    cudaGetSymbolAddress((void**)&attn3, g_attn3);
    cudaGetSymbolAddress((void**)&x13,   g_x13);
    cudaGetSymbolAddress((void**)&h3,    g_h3);
    cudaGetSymbolAddress((void**)&wq3,   g_wqkv3);
    cudaGetSymbolAddress((void**)&wo3,   g_wout3);
    cudaGetSymbolAddress((void**)&w13,   g_wfc13);
    cudaGetSymbolAddress((void**)&w23,   g_wfc23);

    cudaFuncSetAttribute(flash_kernel, cudaFuncAttributeMaxDynamicSharedMemorySize, FA_SMEM);
    cudaFuncSetAttribute(gemm_mma_kernel<0>, cudaFuncAttributeMaxDynamicSharedMemorySize, GEMM_SMEM);
    cudaFuncSetAttribute(gemm_mma_kernel<1>, cudaFuncAttributeMaxDynamicSharedMemorySize, GEMM_SMEM);

    // weight splits (B-side layout: [hi|hi|lo])
    split3_kernel<0><<<3 * Esz, 256>>>(w_qkv, wq3, Esz);
    split3_kernel<0><<<Esz, 256>>>(w_out, wo3, Esz);
    split3_kernel<0><<<FFsz, 256>>>(w_fc1, w13, Esz);
    split3_kernel<0><<<Esz, 256>>>(w_fc2, w23, FFsz);

    // 1) qkv = x @ w_qkv^T + b_qkv
    split3_kernel<1><<<Msz, 256>>>(x, x3, Esz);
    gemm_mma_kernel<0><<<dim3(3 * Esz / 128, Msz / 128), 256, GEMM_SMEM>>>(x3, wq3, b_qkv, qkv, 3 * Esz, 3 * Esz);
    // 2) attention
    flash_kernel<<<dim3(Ssz / 64, Hsz, Bsz), 256, FA_SMEM>>>(qkv, attn);
    // 3) proj = attn @ w_out^T + b_out
    split3_kernel<1><<<Msz, 256>>>(attn, attn3, Esz);
    gemm_mma_kernel<0><<<dim3(Esz / 128, Msz / 128), 256, GEMM_SMEM>>>(attn3, wo3, b_out, proj, Esz, 3 * Esz);
    // 4) x1 = LN(x + proj)
    add_ln_kernel<<<Msz, 256>>>(x, proj, g1, beta1, x1);
    // 5) h = gelu(x1 @ w_fc1^T + b_fc1)
    split3_kernel<1><<<Msz, 256>>>(x1, x13, Esz);
    gemm_mma_kernel<1><<<dim3(FFsz / 128, Msz / 128), 256, GEMM_SMEM>>>(x13, w13, b_fc1, hbuf, FFsz, 3 * Esz);
    // 6) ff = h @ w_fc2^T + b_fc2
    split3_kernel<1><<<Msz, 256>>>(hbuf, h3, FFsz);
    gemm_mma_kernel<0><<<dim3(Esz / 128, Msz / 128), 256, GEMM_SMEM>>>(h3, w23, b_fc2, ff, Esz, 3 * FFsz);
    // 7) out = LN(x1 + ff)
    add_ln_kernel<<<Msz, 256>>>(x1, ff, g2, beta2, (float*)d_out);
}

// round 4
// speedup vs baseline: 2.5436x; 1.3445x over previous
#include <cuda_runtime.h>
#include <cuda_bf16.h>
#include <math.h>
#include <stdint.h>

// Problem dims (fixed by the reference)
#define Bsz 2
#define Ssz 2048
#define Esz 1024
#define Hsz 16
#define Dsz 64
#define FFsz 4096
#define Msz (Bsz*Ssz)   // 4096 tokens

// ===================== helpers ===============================================
__device__ __forceinline__ uint32_t smem_to_u32(const void* p) {
    uint32_t a;
    asm("{ .reg .u64 t; cvta.to.shared.u64 t, %1; cvt.u32.u64 %0, t; }" : "=r"(a) : "l"(p));
    return a;
}
#define CPASYNC16(saddr, gptr) \
    asm volatile("cp.async.cg.shared.global [%0], [%1], 16;" :: "r"((uint32_t)(saddr)), "l"(gptr))
#define CPASYNC_COMMIT() asm volatile("cp.async.commit_group;" ::: "memory")
#define CPASYNC_WAIT2() asm volatile("cp.async.wait_group 2;" ::: "memory")

__device__ __forceinline__ void ldmatrix_x4(uint32_t& r0, uint32_t& r1, uint32_t& r2, uint32_t& r3,
                                            uint32_t addr) {
    asm volatile("ldmatrix.sync.aligned.m8n8.x4.shared.b16 {%0,%1,%2,%3}, [%4];"
        : "=r"(r0), "=r"(r1), "=r"(r2), "=r"(r3) : "r"(addr));
}
__device__ __forceinline__ void mma16816(float* d, const uint32_t* a, const uint32_t* b) {
    asm volatile("mma.sync.aligned.m16n8k16.row.col.f32.bf16.bf16.f32 "
        "{%0,%1,%2,%3}, {%4,%5,%6,%7}, {%8,%9}, {%0,%1,%2,%3};"
        : "+f"(d[0]), "+f"(d[1]), "+f"(d[2]), "+f"(d[3])
        : "r"(a[0]), "r"(a[1]), "r"(a[2]), "r"(a[3]), "r"(b[0]), "r"(b[1]));
}
__device__ __forceinline__ uint32_t pkbf(__nv_bfloat16 a, __nv_bfloat16 b) {
    __nv_bfloat162 t(a, b);   // a = low half (lower address)
    return *(uint32_t*)&t;
}
__device__ __forceinline__ void sts32(uint32_t addr, uint32_t v) {
    asm volatile("st.shared.b32 [%0], %1;" :: "r"(addr), "r"(v) : "memory");
}
__device__ __forceinline__ void sts64v(uint32_t addr, uint32_t a, uint32_t b) {
    asm volatile("st.shared.v2.b32 [%0], {%1,%2};" :: "r"(addr), "r"(a), "r"(b) : "memory");
}
// swizzled address: row-major, row bytes rb (multiple of 128), XOR within 128B blocks
__device__ __forceinline__ uint32_t swadr(uint32_t row, uint32_t rb, uint32_t c) {
    return row * rb + (c & ~127u) + ((c & 127u) ^ ((row & 7u) * 16u));
}

// ===================== scratch (device globals) ==============================
__device__ float g_qkv[(size_t)Msz * 3 * Esz];
__device__ float g_proj[(size_t)Msz * Esz];
__device__ float g_x1[(size_t)Msz * Esz];
__device__ float g_ff[(size_t)Msz * Esz];
// bf16x3 operands
__device__ __nv_bfloat16 g_x3[(size_t)Msz * 3 * Esz];
__device__ __nv_bfloat16 g_attn3[(size_t)Msz * 3 * Esz];
__device__ __nv_bfloat16 g_x13[(size_t)Msz * 3 * Esz];
__device__ __nv_bfloat16 g_h3[(size_t)Msz * 3 * FFsz];
__device__ __nv_bfloat16 g_wqkv3[(size_t)(3 * Esz) * 3 * Esz];
__device__ __nv_bfloat16 g_wout3[(size_t)Esz * 3 * Esz];
__device__ __nv_bfloat16 g_wfc13[(size_t)FFsz * 3 * Esz];
__device__ __nv_bfloat16 g_wfc23[(size_t)Esz * 3 * FFsz];

// ===================== bf16x3 split ==========================================
// ATYPE=1 -> [hi | lo | hi]  (A-side), ATYPE=0 -> [hi | hi | lo]  (B-side)
template<int ATYPE>
__global__ __launch_bounds__(256)
void split3_kernel(const float* __restrict__ src, __nv_bfloat16* __restrict__ dst, int K)
{
    const int row = blockIdx.x;
    const float* s = src + (size_t)row * K;
    __nv_bfloat16* d = dst + (size_t)row * 3 * K;
    for (int k = threadIdx.x; k < K; k += 256) {
        const float x = s[k];
        const __nv_bfloat16 h = __float2bfloat16(x);
        const __nv_bfloat16 l = __float2bfloat16(x - __bfloat162float(h));
        if (ATYPE) { d[k] = h; d[K + k] = l; d[2 * K + k] = h; }
        else       { d[k] = h; d[K + k] = h; d[2 * K + k] = l; }
    }
}

// ===================== HMMA bf16 GEMM ========================================
// C[Msz,N] = A[Msz,K3]*B[N,K3]^T + bias.
// MODE 0: fp32 out. MODE 2: GELU + bf16x3 (A-layout [hi|lo|hi]) out to C3.
#define NBUF 3
#define STAGE_BYTES (128 * 128)
#define GEMM_SMEM (NBUF * 2 * STAGE_BYTES)

template<int MODE>
__global__ __launch_bounds__(256)
void gemm_mma_kernel(const __nv_bfloat16* __restrict__ A, const __nv_bfloat16* __restrict__ Bm,
                     const float* __restrict__ bias, float* __restrict__ C,
                     __nv_bfloat16* __restrict__ C3, int N, int K3)
{
    extern __shared__ __align__(1024) char smem[];
    const uint32_t sbase = smem_to_u32(smem);
    const int tid = threadIdx.x;
    const int lane = tid & 31;
    const int wid = tid >> 5;
    const int wm = wid & 3;
    const int wn = wid >> 2;
    const int bx = blockIdx.x, by = blockIdx.y;

    uint32_t st_off[4];
    #pragma unroll
    for (int t = 0; t < 4; t++) {
        const int idx = tid + t * 256;
        const int row = idx >> 3;
        const int c = (idx & 7) * 16;
        st_off[t] = (uint32_t)(row * 128 + (c ^ ((row & 7) * 16)));
    }
    const size_t ldb = (size_t)K3 * 2;
    const char* Agp[4];
    const char* Bgp[4];
    #pragma unroll
    for (int t = 0; t < 4; t++) {
        const int idx = tid + t * 256;
        Agp[t] = (const char*)A + (size_t)(by * 128 + (idx >> 3)) * ldb + (idx & 7) * 16;
        Bgp[t] = (const char*)Bm + (size_t)(bx * 128 + (idx >> 3)) * ldb + (idx & 7) * 16;
    }

    const uint32_t colxor = (uint32_t)((lane & 7) * 16);
    const uint32_t a_rowbase = (uint32_t)((wm * 32 + (lane & 15)) * 128);
    const uint32_t a_part = (uint32_t)((lane >> 4) * 16);
    const uint32_t b_rowbase = (uint32_t)((wn * 64 + ((lane >> 4) << 3) + (lane & 7)) * 128);
    const uint32_t b_part = (uint32_t)(((lane >> 3) & 1) * 16);

    float acc[2][8][4];
    #pragma unroll
    for (int i = 0; i < 2; i++)
        #pragma unroll
        for (int j = 0; j < 8; j++)
            #pragma unroll
            for (int u = 0; u < 4; u++) acc[i][j][u] = 0.0f;

    const int S = K3 / 64;

    #pragma unroll
    for (int p = 0; p < NBUF; p++) {
        const uint32_t ab = sbase + p * 2 * STAGE_BYTES;
        const uint32_t bb = ab + STAGE_BYTES;
        #pragma unroll
        for (int t = 0; t < 4; t++) {
            CPASYNC16(ab + st_off[t], Agp[t] + (size_t)p * 128);
            CPASYNC16(bb + st_off[t], Bgp[t] + (size_t)p * 128);
        }
        CPASYNC_COMMIT();
    }

    #pragma unroll 1
    for (int s = 0; s < S; s++) {
        CPASYNC_WAIT2();
        __syncthreads();
        const uint32_t ab = sbase + (s % NBUF) * 2 * STAGE_BYTES;
        const uint32_t bb = ab + STAGE_BYTES;

        #pragma unroll
        for (int k = 0; k < 4; k++) {
            const uint32_t kb = (uint32_t)(k * 32);
            uint32_t a[2][4], b[8][2];
            #pragma unroll
            for (int i = 0; i < 2; i++)
                ldmatrix_x4(a[i][0], a[i][1], a[i][2], a[i][3],
                            ab + a_rowbase + (uint32_t)(i * 2048) + ((kb + a_part) ^ colxor));
            #pragma unroll
            for (int jp = 0; jp < 4; jp++) {
                uint32_t r0, r1, r2, r3;
                ldmatrix_x4(r0, r1, r2, r3,
                            bb + b_rowbase + (uint32_t)(jp * 2048) + ((kb + b_part) ^ colxor));
                b[2 * jp][0] = r0; b[2 * jp][1] = r1;
                b[2 * jp + 1][0] = r2; b[2 * jp + 1][1] = r3;
            }
            #pragma unroll
            for (int i = 0; i < 2; i++)
                #pragma unroll
                for (int j = 0; j < 8; j++)
                    mma16816(acc[i][j], a[i], b[j]);
        }
        __syncthreads();
        if (s + NBUF < S) {
            const int sn = s + NBUF;
            #pragma unroll
            for (int t = 0; t < 4; t++) {
                CPASYNC16(ab + st_off[t], Agp[t] + (size_t)sn * 128);
                CPASYNC16(bb + st_off[t], Bgp[t] + (size_t)sn * 128);
            }
            CPASYNC_COMMIT();
        }
    }

    // ---- epilogue ----
    const int row0 = by * 128 + wm * 32 + (lane >> 2);
    const int col0 = bx * 128 + wn * 64 + (lane & 3) * 2;
    #pragma unroll
    for (int j = 0; j < 8; j++) {
        const int col = col0 + j * 8;
        const float2 bv = *(const float2*)&bias[col];
        #pragma unroll
        for (int i = 0; i < 2; i++) {
            #pragma unroll
            for (int half = 0; half < 2; half++) {
                const int row = row0 + i * 16 + half * 8;
                float v0 = acc[i][j][half * 2 + 0] + bv.x;
                float v1 = acc[i][j][half * 2 + 1] + bv.y;
                if (MODE == 2) {
                    v0 = 0.5f * v0 * (1.0f + erff(v0 * 0.70710678118654752f));
                    v1 = 0.5f * v1 * (1.0f + erff(v1 * 0.70710678118654752f));
                    const __nv_bfloat16 h0 = __float2bfloat16(v0);
                    const __nv_bfloat16 h1 = __float2bfloat16(v1);
                    const __nv_bfloat16 l0 = __float2bfloat16(v0 - __bfloat162float(h0));
                    const __nv_bfloat16 l1 = __float2bfloat16(v1 - __bfloat162float(h1));
                    __nv_bfloat16* base = C3 + (size_t)row * (3 * N);
                    *(__nv_bfloat162*)(base + col) = __nv_bfloat162(h0, h1);
                    *(__nv_bfloat162*)(base + N + col) = __nv_bfloat162(l0, l1);
                    *(__nv_bfloat162*)(base + 2 * N + col) = __nv_bfloat162(h0, h1);
                } else {
                    *(float2*)(C + (size_t)row * N + col) = make_float2(v0, v1);
                }
            }
        }
    }
}

// ===================== HMMA flash attention ==================================
// grid (S/128, H, B), 256 threads (8 warps: 4 m-warps x 2 n-warps).
// S = Q K^T via bf16x3 (K-ext = 192). PV via bf16 P duplicated vs (vh,vl)
// interleaved V columns (k-ext = 128). Online softmax in fp32 fragments.
// Writes attn3 bf16x3 (A-layout) directly.
#define SQ3 0
#define SK3 (128*384)             // 49152
#define SVT (SK3 + 64*384)        // 73728  (Vt: 64 d-rows x 256B)
#define SPS (SVT + 64*256)        // 90112  (Ps: 128 rows x 256B)
#define SST (SPS + 128*256)       // 122880 (stats)
#define AT_SMEM (SST + 4096)      // 126976

__global__ __launch_bounds__(256)
void flash_mma_kernel(const float* __restrict__ qkv, __nv_bfloat16* __restrict__ attn3)
{
    extern __shared__ __align__(1024) char sm_[];
    const uint32_t sb = smem_to_u32(sm_);
    float* mS  = (float*)(sm_ + SST);
    float* lS  = mS + 128;
    float* cS  = mS + 256;
    float* rmx = mS + 384;   // [2][128]
    float* rsm = mS + 640;   // [2][128]

    const int tid = threadIdx.x, lane = tid & 31, wid = tid >> 5;
    const int wm = wid & 3, wn = wid >> 2;
    const int qb = blockIdx.x, h = blockIdx.y, b = blockIdx.z;

    const float* qp = qkv + ((size_t)b * Ssz + (size_t)qb * 128) * (3 * Esz) + h * Dsz;
    const float* kp = qkv + (size_t)b * Ssz * (3 * Esz) + Esz + h * Dsz;
    const float* vp = kp + Esz;

    // ---- Q3 load: 128 rows x [qh|ql|qh] (384B rows) ----
    #pragma unroll
    for (int it = 0; it < 16; it++) {
        const int idx = tid + it * 256;
        const int r = idx >> 5, d2 = (idx & 31) * 2;
        const float2 f = *(const float2*)(qp + (size_t)r * 3072 + d2);
        const __nv_bfloat16 h0 = __float2bfloat16(f.x), h1 = __float2bfloat16(f.y);
        const __nv_bfloat16 l0 = __float2bfloat16(f.x - __bfloat162float(h0));
        const __nv_bfloat16 l1 = __float2bfloat16(f.y - __bfloat162float(h1));
        const uint32_t hp = pkbf(h0, h1), lp = pkbf(l0, l1);
        sts32(sb + SQ3 + swadr(r, 384, 2 * d2), hp);
        sts32(sb + SQ3 + swadr(r, 384, 128 + 2 * d2), lp);
        sts32(sb + SQ3 + swadr(r, 384, 256 + 2 * d2), hp);
    }
    if (tid < 128) { mS[tid] = -INFINITY; lS[tid] = 0.0f; }

    // fragment lane components
    const int a_row = lane & 15;
    const int a_part = (lane >> 4) * 16;
    const int b_rowo = ((lane >> 4) << 3) + (lane & 7);
    const int b_part = ((lane >> 3) & 1) * 16;

    float o[2][4][4];
    #pragma unroll
    for (int i = 0; i < 2; i++)
        #pragma unroll
        for (int j = 0; j < 4; j++)
            #pragma unroll
            for (int u = 0; u < 4; u++) o[i][j][u] = 0.0f;

    #pragma unroll 1
    for (int kb = 0; kb < Ssz / 64; kb++) {
        __syncthreads();
        // ---- load K3 (64 x [kh|kh|kl], 384B rows) + Vt (64 d-rows x (vh,vl) pairs) ----
        #pragma unroll
        for (int it = 0; it < 8; it++) {
            const int idx = tid + it * 256;
            const int j = idx >> 5, d2 = (idx & 31) * 2;
            const size_t go = (size_t)(kb * 64 + j) * 3072 + d2;
            const float2 kf = *(const float2*)(kp + go);
            const __nv_bfloat16 kh0 = __float2bfloat16(kf.x), kh1 = __float2bfloat16(kf.y);
            const __nv_bfloat16 kl0 = __float2bfloat16(kf.x - __bfloat162float(kh0));
            const __nv_bfloat16 kl1 = __float2bfloat16(kf.y - __bfloat162float(kh1));
            const uint32_t khp = pkbf(kh0, kh1), klp = pkbf(kl0, kl1);
            sts32(sb + SK3 + swadr(j, 384, 2 * d2), khp);
            sts32(sb + SK3 + swadr(j, 384, 128 + 2 * d2), khp);
            sts32(sb + SK3 + swadr(j, 384, 256 + 2 * d2), klp);
            const float2 vf = *(const float2*)(vp + go);
            const __nv_bfloat16 vh0 = __float2bfloat16(vf.x);
            const __nv_bfloat16 vl0 = __float2bfloat16(vf.x - __bfloat162float(vh0));
            const __nv_bfloat16 vh1 = __float2bfloat16(vf.y);
            const __nv_bfloat16 vl1 = __float2bfloat16(vf.y - __bfloat162float(vh1));
            sts32(sb + SVT + swadr(d2, 256, 4 * j), pkbf(vh0, vl0));
            sts32(sb + SVT + swadr(d2 + 1, 256, 4 * j), pkbf(vh1, vl1));
        }
        __syncthreads();

        // ---- S = Q3 K3^T (k-ext 192, 12 k-steps), warp tile 32x32 ----
        float s[2][4][4];
        #pragma unroll
        for (int i = 0; i < 2; i++)
            #pragma unroll
            for (int j = 0; j < 4; j++)
                #pragma unroll
                for (int u = 0; u < 4; u++) s[i][j][u] = 0.0f;

        #pragma unroll
        for (int ks = 0; ks < 12; ks++) {
            const uint32_t kbyte = (uint32_t)(ks * 32);
            uint32_t a[2][4], bfr[4][2];
            #pragma unroll
            for (int i = 0; i < 2; i++)
                ldmatrix_x4(a[i][0], a[i][1], a[i][2], a[i][3],
                            sb + SQ3 + swadr((uint32_t)(wm * 32 + i * 16 + a_row), 384, kbyte + a_part));
            #pragma unroll
            for (int jp = 0; jp < 2; jp++) {
                uint32_t r0, r1, r2, r3;
                ldmatrix_x4(r0, r1, r2, r3,
                            sb + SK3 + swadr((uint32_t)(wn * 32 + jp * 16 + b_rowo), 384, kbyte + b_part));
                bfr[2 * jp][0] = r0; bfr[2 * jp][1] = r1;
                bfr[2 * jp + 1][0] = r2; bfr[2 * jp + 1][1] = r3;
            }
            #pragma unroll
            for (int i = 0; i < 2; i++)
                #pragma unroll
                for (int j = 0; j < 4; j++)
                    mma16816(s[i][j], a[i], bfr[j]);
        }

        // ---- scale + per-row max (quad reduce) ----
        #pragma unroll
        for (int i = 0; i < 2; i++)
            #pragma unroll
            for (int j = 0; j < 4; j++)
                #pragma unroll
                for (int u = 0; u < 4; u++) s[i][j][u] *= 0.125f;

        #pragma unroll
        for (int i = 0; i < 2; i++) {
            #pragma unroll
            for (int half = 0; half < 2; half++) {
                float v = -INFINITY;
                #pragma unroll
                for (int j = 0; j < 4; j++)
                    v = fmaxf(v, fmaxf(s[i][j][half * 2], s[i][j][half * 2 + 1]));
                v = fmaxf(v, __shfl_xor_sync(0xffffffffu, v, 1));
                v = fmaxf(v, __shfl_xor_sync(0xffffffffu, v, 2));
                if ((lane & 3) == 0)
                    rmx[wn * 128 + wm * 32 + i * 16 + half * 8 + (lane >> 2)] = v;
            }
        }
        __syncthreads();
        if (tid < 128) {
            const float mo = mS[tid];
            const float mn = fmaxf(mo, fmaxf(rmx[tid], rmx[128 + tid]));
            mS[tid] = mn;
            cS[tid] = __expf(mo - mn);
        }
        __syncthreads();

        // ---- exp, o-rescale, Ps store (duplicated), partial row sums ----
        #pragma unroll
        for (int i = 0; i < 2; i++) {
            #pragma unroll
            for (int half = 0; half < 2; half++) {
                const int rloc = wm * 32 + i * 16 + half * 8 + (lane >> 2);
                const float mn = mS[rloc];
                const float corr = cS[rloc];
                float rs = 0.0f;
                #pragma unroll
                for (int j = 0; j < 4; j++) {
                    const float p0 = __expf(s[i][j][half * 2] - mn);
                    const float p1 = __expf(s[i][j][half * 2 + 1] - mn);
                    rs += p0 + p1;
                    o[i][j][half * 2] *= corr;
                    o[i][j][half * 2 + 1] *= corr;
                    const __nv_bfloat16 pb0 = __float2bfloat16(p0);
                    const __nv_bfloat16 pb1 = __float2bfloat16(p1);
                    const uint32_t col = (uint32_t)(wn * 32 + j * 8 + (lane & 3) * 2);
                    sts64v(sb + SPS + swadr((uint32_t)rloc, 256, 4 * col),
                           pkbf(pb0, pb0), pkbf(pb1, pb1));
                }
                rs += __shfl_xor_sync(0xffffffffu, rs, 1);
                rs += __shfl_xor_sync(0xffffffffu, rs, 2);
                if ((lane & 3) == 0)
                    rsm[wn * 128 + rloc] = rs;
            }
        }
        __syncthreads();
        if (tid < 128)
            lS[tid] = lS[tid] * cS[tid] + rsm[tid] + rsm[128 + tid];

        // ---- O += P_ext * Vt^T (k-ext 128, 8 k-steps), warp tile 32(m)x32(d) ----
        #pragma unroll
        for (int ks = 0; ks < 8; ks++) {
            const uint32_t kbyte = (uint32_t)(ks * 32);
            uint32_t a[2][4], bfr[4][2];
            #pragma unroll
            for (int i = 0; i < 2; i++)
                ldmatrix_x4(a[i][0], a[i][1], a[i][2], a[i][3],
                            sb + SPS + swadr((uint32_t)(wm * 32 + i * 16 + a_row), 256, kbyte + a_part));
            #pragma unroll
            for (int jp = 0; jp < 2; jp++) {
                uint32_t r0, r1, r2, r3;
                ldmatrix_x4(r0, r1, r2, r3,
                            sb + SVT + swadr((uint32_t)(wn * 32 + jp * 16 + b_rowo), 256, kbyte + b_part));
                bfr[2 * jp][0] = r0; bfr[2 * jp][1] = r1;
                bfr[2 * jp + 1][0] = r2; bfr[2 * jp + 1][1] = r3;
            }
            #pragma unroll
            for (int i = 0; i < 2; i++)
                #pragma unroll
                for (int j = 0; j < 4; j++)
                    mma16816(o[i][j], a[i], bfr[j]);
        }
    }
    __syncthreads();

    // ---- epilogue: write attn3 [hi|lo|hi] ----
    #pragma unroll
    for (int i = 0; i < 2; i++) {
        #pragma unroll
        for (int half = 0; half < 2; half++) {
            const int rloc = wm * 32 + i * 16 + half * 8 + (lane >> 2);
            const float inv = 1.0f / lS[rloc];
            const size_t rowg = (size_t)b * Ssz + (size_t)qb * 128 + rloc;
            __nv_bfloat16* base = attn3 + rowg * 3072;
            #pragma unroll
            for (int j = 0; j < 4; j++) {
                const int col = h * 64 + wn * 32 + j * 8 + (lane & 3) * 2;
                const float v0 = o[i][j][half * 2] * inv;
                const float v1 = o[i][j][half * 2 + 1] * inv;
                const __nv_bfloat16 h0 = __float2bfloat16(v0);
                const __nv_bfloat16 h1 = __float2bfloat16(v1);
                const __nv_bfloat16 l0 = __float2bfloat16(v0 - __bfloat162float(h0));
                const __nv_bfloat16 l1 = __float2bfloat16(v1 - __bfloat162float(h1));
                *(__nv_bfloat162*)(base + col) = __nv_bfloat162(h0, h1);
                *(__nv_bfloat162*)(base + 1024 + col) = __nv_bfloat162(l0, l1);
                *(__nv_bfloat162*)(base + 2048 + col) = __nv_bfloat162(h0, h1);
            }
        }
    }
}

// ===================== fused residual-add + LayerNorm (+x3 out) ==============
__global__ __launch_bounds__(256)
void add_ln_kernel(const float* __restrict__ A, const float* __restrict__ Bv,
                   const float* __restrict__ g, const float* __restrict__ be,
                   float* __restrict__ Y, __nv_bfloat16* __restrict__ Y3)
{
    const int row = blockIdx.x;
    const int tid = threadIdx.x;
    const float4 av = ((const float4*)(A + (size_t)row * Esz))[tid];
    const float4 bv = ((const float4*)(Bv + (size_t)row * Esz))[tid];
    const float v0 = av.x + bv.x, v1 = av.y + bv.y, v2 = av.z + bv.z, v3 = av.w + bv.w;

    float s = v0 + v1 + v2 + v3;
    float s2 = v0 * v0 + v1 * v1 + v2 * v2 + v3 * v3;
    #pragma unroll
    for (int o = 16; o; o >>= 1) {
        s += __shfl_xor_sync(0xffffffffu, s, o);
        s2 += __shfl_xor_sync(0xffffffffu, s2, o);
    }
    __shared__ float ss[8], ss2[8];
    const int w = tid >> 5, ln = tid & 31;
    if (ln == 0) { ss[w] = s; ss2[w] = s2; }
    __syncthreads();
    if (tid < 8) {
        s = ss[tid]; s2 = ss2[tid];
        #pragma unroll
        for (int o = 4; o; o >>= 1) {
            s += __shfl_xor_sync(0x000000ffu, s, o);
            s2 += __shfl_xor_sync(0x000000ffu, s2, o);
        }
        if (tid == 0) { ss[0] = s; ss2[0] = s2; }
    }
    __syncthreads();
    const float mean = ss[0] * (1.0f / Esz);
    const float var = ss2[0] * (1.0f / Esz) - mean * mean;
    const float rstd = rsqrtf(var + 1e-5f);

    const float4 gv = ((const float4*)g)[tid];
    const float4 bev = ((const float4*)be)[tid];
    float4 o4;
    o4.x = (v0 - mean) * rstd * gv.x + bev.x;
    o4.y = (v1 - mean) * rstd * gv.y + bev.y;
    o4.z = (v2 - mean) * rstd * gv.z + bev.z;
    o4.w = (v3 - mean) * rstd * gv.w + bev.w;
    ((float4*)(Y + (size_t)row * Esz))[tid] = o4;

    if (Y3) {
        const float vv[4] = {o4.x, o4.y, o4.z, o4.w};
        __nv_bfloat16 hh[4], ll[4];
        #pragma unroll
        for (int u = 0; u < 4; u++) {
            hh[u] = __float2bfloat16(vv[u]);
            ll[u] = __float2bfloat16(vv[u] - __bfloat162float(hh[u]));
        }
        __nv_bfloat16* base = Y3 + (size_t)row * 3072 + tid * 4;
        *(__nv_bfloat162*)(base) = __nv_bfloat162(hh[0], hh[1]);
        *(__nv_bfloat162*)(base + 2) = __nv_bfloat162(hh[2], hh[3]);
        *(__nv_bfloat162*)(base + 1024) = __nv_bfloat162(ll[0], ll[1]);
        *(__nv_bfloat162*)(base + 1026) = __nv_bfloat162(ll[2], ll[3]);
        *(__nv_bfloat162*)(base + 2048) = __nv_bfloat162(hh[0], hh[1]);
        *(__nv_bfloat162*)(base + 2050) = __nv_bfloat162(hh[2], hh[3]);
    }
}

// ===================== launch ================================================
extern "C" void kernel_launch(void* const* d_in, const int* in_sizes, int n_in,
                              void* d_out, int out_size)
{
    (void)in_sizes; (void)n_in; (void)out_size;
    const float* x     = (const float*)d_in[0];
    const float* w_qkv = (const float*)d_in[1];
    const float* b_qkv = (const float*)d_in[2];
    const float* w_out = (const float*)d_in[3];
    const float* b_out = (const float*)d_in[4];
    const float* g1    = (const float*)d_in[5];
    const float* beta1 = (const float*)d_in[6];
    const float* w_fc1 = (const float*)d_in[7];
    const float* b_fc1 = (const float*)d_in[8];
    const float* w_fc2 = (const float*)d_in[9];
    const float* b_fc2 = (const float*)d_in[10];
    const float* g2    = (const float*)d_in[11];
    const float* beta2 = (const float*)d_in[12];

    float *qkv, *proj, *x1, *ff;
    cudaGetSymbolAddress((void**)&qkv,  g_qkv);
    cudaGetSymbolAddress((void**)&proj, g_proj);
    cudaGetSymbolAddress((void**)&x1,   g_x1);
    cudaGetSymbolAddress((void**)&ff,   g_ff);
    __nv_bfloat16 *x3, *attn3, *x13, *h3, *wq3, *wo3, *w13, *w23;
    cudaGetSymbolAddress((void**)&x3,    g_x3);
    cudaGetSymbolAddress((void**)&attn3, g_attn3);
    cudaGetSymbolAddress((void**)&x13,   g_x13);
    cudaGetSymbolAddress((void**)&h3,    g_h3);
    cudaGetSymbolAddress((void**)&wq3,   g_wqkv3);
    cudaGetSymbolAddress((void**)&wo3,   g_wout3);
    cudaGetSymbolAddress((void**)&w13,   g_wfc13);
    cudaGetSymbolAddress((void**)&w23,   g_wfc23);

    cudaFuncSetAttribute(flash_mma_kernel, cudaFuncAttributeMaxDynamicSharedMemorySize, AT_SMEM);
    cudaFuncSetAttribute(gemm_mma_kernel<0>, cudaFuncAttributeMaxDynamicSharedMemorySize, GEMM_SMEM);
    cudaFuncSetAttribute(gemm_mma_kernel<2>, cudaFuncAttributeMaxDynamicSharedMemorySize, GEMM_SMEM);

    // weight splits (B-side [hi|hi|lo]); input split (A-side [hi|lo|hi])
    split3_kernel<0><<<3 * Esz, 256>>>(w_qkv, wq3, Esz);
    split3_kernel<0><<<Esz, 256>>>(w_out, wo3, Esz);
    split3_kernel<0><<<FFsz, 256>>>(w_fc1, w13, Esz);
    split3_kernel<0><<<Esz, 256>>>(w_fc2, w23, FFsz);
    split3_kernel<1><<<Msz, 256>>>(x, x3, Esz);

    // 1) qkv = x @ w_qkv^T + b_qkv
    gemm_mma_kernel<0><<<dim3(3 * Esz / 128, Msz / 128), 256, GEMM_SMEM>>>(x3, wq3, b_qkv, qkv, nullptr, 3 * Esz, 3 * Esz);
    // 2) attention (HMMA flash) -> attn3 (bf16x3)
    flash_mma_kernel<<<dim3(Ssz / 128, Hsz, Bsz), 256, AT_SMEM>>>(qkv, attn3);
    // 3) proj = attn @ w_out^T + b_out
    gemm_mma_kernel<0><<<dim3(Esz / 128, Msz / 128), 256, GEMM_SMEM>>>(attn3, wo3, b_out, proj, nullptr, Esz, 3 * Esz);
    // 4) x1 = LN(x + proj)  (+ x13 bf16x3)
    add_ln_kernel<<<Msz, 256>>>(x, proj, g1, beta1, x1, x13);
    // 5) h3 = bf16x3(gelu(x1 @ w_fc1^T + b_fc1))
    gemm_mma_kernel<2><<<dim3(FFsz / 128, Msz / 128), 256, GEMM_SMEM>>>(x13, w13, b_fc1, nullptr, h3, FFsz, 3 * Esz);
    // 6) ff = h @ w_fc2^T + b_fc2
    gemm_mma_kernel<0><<<dim3(Esz / 128, Msz / 128), 256, GEMM_SMEM>>>(h3, w23, b_fc2, ff, nullptr, Esz, 3 * FFsz);
    // 7) out = LN(x1 + ff)
    add_ln_kernel<<<Msz, 256>>>(x1, ff, g2, beta2, (float*)d_out, nullptr);
}

// round 5
// speedup vs baseline: 4.0813x; 1.6045x over previous
#include <cuda_runtime.h>
#include <cuda_fp16.h>
#include <math.h>
#include <stdint.h>

// Problem dims (fixed by the reference)
#define Bsz 2
#define Ssz 2048
#define Esz 1024
#define Hsz 16
#define Dsz 64
#define FFsz 4096
#define Msz (Bsz*Ssz)   // 4096 tokens

// ===================== helpers ===============================================
__device__ __forceinline__ uint32_t smem_to_u32(const void* p) {
    uint32_t a;
    asm("{ .reg .u64 t; cvta.to.shared.u64 t, %1; cvt.u32.u64 %0, t; }" : "=r"(a) : "l"(p));
    return a;
}
#define CPASYNC16(saddr, gptr) \
    asm volatile("cp.async.cg.shared.global [%0], [%1], 16;" :: "r"((uint32_t)(saddr)), "l"(gptr))
#define CPASYNC_COMMIT() asm volatile("cp.async.commit_group;" ::: "memory")
#define CPASYNC_WAIT2() asm volatile("cp.async.wait_group 2;" ::: "memory")
#define CPASYNC_WAIT0() asm volatile("cp.async.wait_group 0;" ::: "memory")

__device__ __forceinline__ void ldmatrix_x4(uint32_t& r0, uint32_t& r1, uint32_t& r2, uint32_t& r3,
                                            uint32_t addr) {
    asm volatile("ldmatrix.sync.aligned.m8n8.x4.shared.b16 {%0,%1,%2,%3}, [%4];"
        : "=r"(r0), "=r"(r1), "=r"(r2), "=r"(r3) : "r"(addr));
}
__device__ __forceinline__ void mma16816(float* d, const uint32_t* a, const uint32_t* b) {
    asm volatile("mma.sync.aligned.m16n8k16.row.col.f32.f16.f16.f32 "
        "{%0,%1,%2,%3}, {%4,%5,%6,%7}, {%8,%9}, {%0,%1,%2,%3};"
        : "+f"(d[0]), "+f"(d[1]), "+f"(d[2]), "+f"(d[3])
        : "r"(a[0]), "r"(a[1]), "r"(a[2]), "r"(a[3]), "r"(b[0]), "r"(b[1]));
}
__device__ __forceinline__ uint32_t pkh(__half a, __half b) {
    __half2 t = __halves2half2(a, b);
    return *(uint32_t*)&t;
}
__device__ __forceinline__ void sts64v(uint32_t addr, uint32_t a, uint32_t b) {
    asm volatile("st.shared.v2.b32 [%0], {%1,%2};" :: "r"(addr), "r"(a), "r"(b) : "memory");
}
// swizzled address: row-major, row bytes rb (multiple of 128), XOR within 128B blocks
__device__ __forceinline__ uint32_t swadr(uint32_t row, uint32_t rb, uint32_t c) {
    return row * rb + (c & ~127u) + ((c & 127u) ^ ((row & 7u) * 16u));
}

// ===================== scratch (device globals) ==============================
__device__ float g_proj[(size_t)Msz * Esz];
__device__ float g_x1[(size_t)Msz * Esz];
__device__ float g_ff[(size_t)Msz * Esz];
// fp16x2 operands / pre-split attention inputs
__device__ __half g_q2[(size_t)Msz * 2 * Esz];        // [tok][h][qh(64)|ql(64)]
__device__ __half g_k2[(size_t)Msz * Esz];            // [tok][h][kh(64)]
__device__ __half g_v2t[(size_t)Bsz * Hsz * 64 * Ssz * 2];  // [b,h,d,s] (vh,vl) pairs
__device__ __half g_attn2[(size_t)Msz * 2 * Esz];     // [ah|al]
__device__ __half g_x2[(size_t)Msz * 2 * Esz];
__device__ __half g_x12[(size_t)Msz * 2 * Esz];
__device__ __half g_h2[(size_t)Msz * 2 * FFsz];
__device__ __half g_wqkv2[(size_t)(3 * Esz) * 2 * Esz];
__device__ __half g_wout2[(size_t)Esz * 2 * Esz];
__device__ __half g_wfc12[(size_t)FFsz * 2 * Esz];
__device__ __half g_wfc22[(size_t)Esz * 2 * FFsz];

// ===================== fp16x2 split ==========================================
// ATYPE=1 -> [hi | lo]  (A-side), ATYPE=0 -> [hi | hi]  (B-side, duplicated)
template<int ATYPE>
__global__ __launch_bounds__(256)
void split2_kernel(const float* __restrict__ src, __half* __restrict__ dst, int K)
{
    const int row = blockIdx.x;
    const float* s = src + (size_t)row * K;
    __half* d = dst + (size_t)row * 2 * K;
    for (int k = threadIdx.x; k < K; k += 256) {
        const float x = s[k];
        const __half h = __float2half_rn(x);
        d[k] = h;
        if (ATYPE) d[K + k] = __float2half_rn(x - __half2float(h));
        else       d[K + k] = h;
    }
}

// ===================== HMMA fp16 GEMM ========================================
// C[Msz,N] = A[Msz,K2]*B[N,K2]^T + bias.
// MODE 0: fp32 out C. MODE 1: qkv split epilogue (q2/k2/v2t). MODE 2: GELU +
// fp16x2 [hi|lo] out to C3 (stride 2N).
#define NBUF 3
#define STAGE_BYTES (128 * 128)
#define GEMM_SMEM (NBUF * 2 * STAGE_BYTES)

template<int MODE>
__global__ __launch_bounds__(256)
void gemm_mma_kernel(const __half* __restrict__ A, const __half* __restrict__ Bm,
                     const float* __restrict__ bias, float* __restrict__ C,
                     __half* __restrict__ C3,
                     __half* __restrict__ q2p, __half* __restrict__ k2p, __half* __restrict__ v2tp,
                     int N, int K2)
{
    extern __shared__ __align__(1024) char smem[];
    const uint32_t sbase = smem_to_u32(smem);
    const int tid = threadIdx.x;
    const int lane = tid & 31;
    const int wid = tid >> 5;
    const int wm = wid & 3;
    const int wn = wid >> 2;
    const int bx = blockIdx.x, by = blockIdx.y;

    uint32_t st_off[4];
    #pragma unroll
    for (int t = 0; t < 4; t++) {
        const int idx = tid + t * 256;
        const int row = idx >> 3;
        const int c = (idx & 7) * 16;
        st_off[t] = (uint32_t)(row * 128 + (c ^ ((row & 7) * 16)));
    }
    const size_t ldb = (size_t)K2 * 2;
    const char* Agp[4];
    const char* Bgp[4];
    #pragma unroll
    for (int t = 0; t < 4; t++) {
        const int idx = tid + t * 256;
        Agp[t] = (const char*)A + (size_t)(by * 128 + (idx >> 3)) * ldb + (idx & 7) * 16;
        Bgp[t] = (const char*)Bm + (size_t)(bx * 128 + (idx >> 3)) * ldb + (idx & 7) * 16;
    }

    const uint32_t colxor = (uint32_t)((lane & 7) * 16);
    const uint32_t a_rowbase = (uint32_t)((wm * 32 + (lane & 15)) * 128);
    const uint32_t a_part = (uint32_t)((lane >> 4) * 16);
    const uint32_t b_rowbase = (uint32_t)((wn * 64 + ((lane >> 4) << 3) + (lane & 7)) * 128);
    const uint32_t b_part = (uint32_t)(((lane >> 3) & 1) * 16);

    float acc[2][8][4];
    #pragma unroll
    for (int i = 0; i < 2; i++)
        #pragma unroll
        for (int j = 0; j < 8; j++)
            #pragma unroll
            for (int u = 0; u < 4; u++) acc[i][j][u] = 0.0f;

    const int S = K2 / 64;

    #pragma unroll
    for (int p = 0; p < NBUF; p++) {
        const uint32_t ab = sbase + p * 2 * STAGE_BYTES;
        const uint32_t bb = ab + STAGE_BYTES;
        #pragma unroll
        for (int t = 0; t < 4; t++) {
            CPASYNC16(ab + st_off[t], Agp[t] + (size_t)p * 128);
            CPASYNC16(bb + st_off[t], Bgp[t] + (size_t)p * 128);
        }
        CPASYNC_COMMIT();
    }

    #pragma unroll 1
    for (int s = 0; s < S; s++) {
        CPASYNC_WAIT2();
        __syncthreads();
        const uint32_t ab = sbase + (s % NBUF) * 2 * STAGE_BYTES;
        const uint32_t bb = ab + STAGE_BYTES;

        #pragma unroll
        for (int k = 0; k < 4; k++) {
            const uint32_t kb = (uint32_t)(k * 32);
            uint32_t a[2][4], b[8][2];
            #pragma unroll
            for (int i = 0; i < 2; i++)
                ldmatrix_x4(a[i][0], a[i][1], a[i][2], a[i][3],
                            ab + a_rowbase + (uint32_t)(i * 2048) + ((kb + a_part) ^ colxor));
            #pragma unroll
            for (int jp = 0; jp < 4; jp++) {
                uint32_t r0, r1, r2, r3;
                ldmatrix_x4(r0, r1, r2, r3,
                            bb + b_rowbase + (uint32_t)(jp * 2048) + ((kb + b_part) ^ colxor));
                b[2 * jp][0] = r0; b[2 * jp][1] = r1;
                b[2 * jp + 1][0] = r2; b[2 * jp + 1][1] = r3;
            }
            #pragma unroll
            for (int i = 0; i < 2; i++)
                #pragma unroll
                for (int j = 0; j < 8; j++)
                    mma16816(acc[i][j], a[i], b[j]);
        }
        __syncthreads();
        if (s + NBUF < S) {
            const int sn = s + NBUF;
            #pragma unroll
            for (int t = 0; t < 4; t++) {
                CPASYNC16(ab + st_off[t], Agp[t] + (size_t)sn * 128);
                CPASYNC16(bb + st_off[t], Bgp[t] + (size_t)sn * 128);
            }
            CPASYNC_COMMIT();
        } else {
            CPASYNC_COMMIT();  // empty group keeps wait_group 2 accounting exact
        }
    }

    // ---- epilogue ----
    const int row0 = by * 128 + wm * 32 + (lane >> 2);
    const int col0 = bx * 128 + wn * 64 + (lane & 3) * 2;
    #pragma unroll
    for (int j = 0; j < 8; j++) {
        const int col = col0 + j * 8;
        const float2 bv = *(const float2*)&bias[col];
        #pragma unroll
        for (int i = 0; i < 2; i++) {
            #pragma unroll
            for (int half = 0; half < 2; half++) {
                const int row = row0 + i * 16 + half * 8;
                float v0 = acc[i][j][half * 2 + 0] + bv.x;
                float v1 = acc[i][j][half * 2 + 1] + bv.y;
                if (MODE == 0) {
                    *(float2*)(C + (size_t)row * N + col) = make_float2(v0, v1);
                } else if (MODE == 2) {
                    v0 = 0.5f * v0 * (1.0f + erff(v0 * 0.70710678118654752f));
                    v1 = 0.5f * v1 * (1.0f + erff(v1 * 0.70710678118654752f));
                    const __half h0 = __float2half_rn(v0);
                    const __half h1 = __float2half_rn(v1);
                    const __half l0 = __float2half_rn(v0 - __half2float(h0));
                    const __half l1 = __float2half_rn(v1 - __half2float(h1));
                    __half* base = C3 + (size_t)row * (2 * N);
                    *(__half2*)(base + col) = __halves2half2(h0, h1);
                    *(__half2*)(base + N + col) = __halves2half2(l0, l1);
                } else {  // MODE 1: qkv split epilogue
                    const int brow = row >> 11;
                    const int srow = row & 2047;
                    const int sec = col >> 10;
                    const int within = col & 1023;
                    const int hh = within >> 6;
                    const int dd = within & 63;
                    const __half h0 = __float2half_rn(v0);
                    const __half h1 = __float2half_rn(v1);
                    if (sec == 0) {
                        const __half l0 = __float2half_rn(v0 - __half2float(h0));
                        const __half l1 = __float2half_rn(v1 - __half2float(h1));
                        __half* qb_ = q2p + (size_t)row * 2048 + hh * 128 + dd;
                        *(__half2*)(qb_) = __halves2half2(h0, h1);
                        *(__half2*)(qb_ + 64) = __halves2half2(l0, l1);
                    } else if (sec == 1) {
                        *(__half2*)(k2p + (size_t)row * 1024 + hh * 64 + dd) = __halves2half2(h0, h1);
                    } else {
                        const __half l0 = __float2half_rn(v0 - __half2float(h0));
                        const __half l1 = __float2half_rn(v1 - __half2float(h1));
                        __half* vb_ = v2tp + ((((size_t)(brow * Hsz + hh) * 64 + dd) * Ssz) + srow) * 2;
                        *(__half2*)vb_ = __halves2half2(h0, l0);
                        *(__half2*)(vb_ + 2 * Ssz) = __halves2half2(h1, l1);
                    }
                }
            }
        }
    }
}

// ===================== HMMA flash attention (fp16x2) =========================
// grid (S/128, H, B), 256 threads (8 warps: 4 m-warps x 2 n-warps).
// S = Q K^T via fp16x2 (k-ext 128). PV via fp16 P duplicated vs (vh,vl)
// interleaved V columns (k-ext 128). All tile fills are cp.async.
#define SQ2 0
#define SK2 32768
#define SVT 49152
#define SPS 65536
#define SST 98304
#define AT_SMEM 102400

__global__ __launch_bounds__(256)
void flash_mma_kernel(const __half* __restrict__ q2, const __half* __restrict__ k2,
                      const __half* __restrict__ v2t, __half* __restrict__ attn2)
{
    extern __shared__ __align__(1024) char sm_[];
    const uint32_t sb = smem_to_u32(sm_);
    float* mS  = (float*)(sm_ + SST);
    float* lS  = mS + 128;
    float* cS  = mS + 256;
    float* rmx = mS + 384;   // [2][128]
    float* rsm = mS + 640;   // [2][128]

    const int tid = threadIdx.x, lane = tid & 31, wid = tid >> 5;
    const int wm = wid & 3, wn = wid >> 2;
    const int qb = blockIdx.x, h = blockIdx.y, b = blockIdx.z;

    const char* qsrc = (const char*)q2 + ((size_t)(b * Ssz + qb * 128) * 2048 + h * 128) * 2;
    const char* ksrc = (const char*)k2 + ((size_t)b * Ssz * 1024 + h * 64) * 2;
    const char* vsrc = (const char*)v2t + ((size_t)(b * Hsz + h) * 64) * Ssz * 4;

    // ---- Q2 fill (cp.async): 128 rows x 256B ----
    #pragma unroll
    for (int it = 0; it < 8; it++) {
        const int idx = tid + it * 256;
        const int r = idx >> 4;
        const int c = (idx & 15) * 16;
        CPASYNC16(sb + SQ2 + swadr(r, 256, c), qsrc + (size_t)r * 4096 + c);
    }
    CPASYNC_COMMIT();
    if (tid < 128) { mS[tid] = -INFINITY; lS[tid] = 0.0f; }

    const int a_row = lane & 15;
    const int a_part = (lane >> 4) * 16;
    const int b_rowo = ((lane >> 4) << 3) + (lane & 7);
    const int b_part = ((lane >> 3) & 1) * 16;

    float o[2][4][4];
    #pragma unroll
    for (int i = 0; i < 2; i++)
        #pragma unroll
        for (int j = 0; j < 4; j++)
            #pragma unroll
            for (int u = 0; u < 4; u++) o[i][j][u] = 0.0f;

    #pragma unroll 1
    for (int kb = 0; kb < Ssz / 64; kb++) {
        __syncthreads();  // K2/VT/PS reuse guard
        // ---- K fill duplicated [kh|kh]: 64 rows x 256B ----
        #pragma unroll
        for (int it = 0; it < 2; it++) {
            const int idx = tid + it * 256;
            const int j = idx >> 3;
            const int c = (idx & 7) * 16;
            const char* src = ksrc + (size_t)(kb * 64 + j) * 2048 + c;
            CPASYNC16(sb + SK2 + swadr(j, 256, c), src);
            CPASYNC16(sb + SK2 + swadr(j, 256, 128 + c), src);
        }
        // ---- Vt fill: 64 d-rows x 256B (tokens kb*64..kb*64+63 pairs) ----
        #pragma unroll
        for (int it = 0; it < 4; it++) {
            const int idx = tid + it * 256;
            const int d = idx >> 4;
            const int c = (idx & 15) * 16;
            CPASYNC16(sb + SVT + swadr(d, 256, c), vsrc + (size_t)d * 8192 + kb * 256 + c);
        }
        CPASYNC_COMMIT();
        CPASYNC_WAIT0();
        __syncthreads();

        // ---- S = Q2 K2^T (8 k-steps), warp tile 32x32 ----
        float s[2][4][4];
        #pragma unroll
        for (int i = 0; i < 2; i++)
            #pragma unroll
            for (int j = 0; j < 4; j++)
                #pragma unroll
                for (int u = 0; u < 4; u++) s[i][j][u] = 0.0f;

        #pragma unroll
        for (int ks = 0; ks < 8; ks++) {
            const uint32_t kbyte = (uint32_t)(ks * 32);
            uint32_t a[2][4], bfr[4][2];
            #pragma unroll
            for (int i = 0; i < 2; i++)
                ldmatrix_x4(a[i][0], a[i][1], a[i][2], a[i][3],
                            sb + SQ2 + swadr((uint32_t)(wm * 32 + i * 16 + a_row), 256, kbyte + a_part));
            #pragma unroll
            for (int jp = 0; jp < 2; jp++) {
                uint32_t r0, r1, r2, r3;
                ldmatrix_x4(r0, r1, r2, r3,
                            sb + SK2 + swadr((uint32_t)(wn * 32 + jp * 16 + b_rowo), 256, kbyte + b_part));
                bfr[2 * jp][0] = r0; bfr[2 * jp][1] = r1;
                bfr[2 * jp + 1][0] = r2; bfr[2 * jp + 1][1] = r3;
            }
            #pragma unroll
            for (int i = 0; i < 2; i++)
                #pragma unroll
                for (int j = 0; j < 4; j++)
                    mma16816(s[i][j], a[i], bfr[j]);
        }

        // ---- scale + per-row max ----
        #pragma unroll
        for (int i = 0; i < 2; i++)
            #pragma unroll
            for (int j = 0; j < 4; j++)
                #pragma unroll
                for (int u = 0; u < 4; u++) s[i][j][u] *= 0.125f;

        #pragma unroll
        for (int i = 0; i < 2; i++) {
            #pragma unroll
            for (int half = 0; half < 2; half++) {
                float v = -INFINITY;
                #pragma unroll
                for (int j = 0; j < 4; j++)
                    v = fmaxf(v, fmaxf(s[i][j][half * 2], s[i][j][half * 2 + 1]));
                v = fmaxf(v, __shfl_xor_sync(0xffffffffu, v, 1));
                v = fmaxf(v, __shfl_xor_sync(0xffffffffu, v, 2));
                if ((lane & 3) == 0)
                    rmx[wn * 128 + wm * 32 + i * 16 + half * 8 + (lane >> 2)] = v;
            }
        }
        __syncthreads();
        if (tid < 128) {
            const float mo = mS[tid];
            const float mn = fmaxf(mo, fmaxf(rmx[tid], rmx[128 + tid]));
            mS[tid] = mn;
            cS[tid] = __expf(mo - mn);
        }
        __syncthreads();

        // ---- exp, o-rescale, Ps store (fp16, duplicated), partial sums ----
        #pragma unroll
        for (int i = 0; i < 2; i++) {
            #pragma unroll
            for (int half = 0; half < 2; half++) {
                const int rloc = wm * 32 + i * 16 + half * 8 + (lane >> 2);
                const float mn = mS[rloc];
                const float corr = cS[rloc];
                float rs = 0.0f;
                #pragma unroll
                for (int j = 0; j < 4; j++) {
                    const float p0 = __expf(s[i][j][half * 2] - mn);
                    const float p1 = __expf(s[i][j][half * 2 + 1] - mn);
                    rs += p0 + p1;
                    o[i][j][half * 2] *= corr;
                    o[i][j][half * 2 + 1] *= corr;
                    const __half pb0 = __float2half_rn(p0);
                    const __half pb1 = __float2half_rn(p1);
                    const uint32_t col = (uint32_t)(wn * 32 + j * 8 + (lane & 3) * 2);
                    sts64v(sb + SPS + swadr((uint32_t)rloc, 256, 4 * col),
                           pkh(pb0, pb0), pkh(pb1, pb1));
                }
                rs += __shfl_xor_sync(0xffffffffu, rs, 1);
                rs += __shfl_xor_sync(0xffffffffu, rs, 2);
                if ((lane & 3) == 0)
                    rsm[wn * 128 + rloc] = rs;
            }
        }
        __syncthreads();
        if (tid < 128)
            lS[tid] = lS[tid] * cS[tid] + rsm[tid] + rsm[128 + tid];

        // ---- O += P_ext * Vt^T (8 k-steps), warp tile 32(m)x32(d) ----
        #pragma unroll
        for (int ks = 0; ks < 8; ks++) {
            const uint32_t kbyte = (uint32_t)(ks * 32);
            uint32_t a[2][4], bfr[4][2];
            #pragma unroll
            for (int i = 0; i < 2; i++)
                ldmatrix_x4(a[i][0], a[i][1], a[i][2], a[i][3],
                            sb + SPS + swadr((uint32_t)(wm * 32 + i * 16 + a_row), 256, kbyte + a_part));
            #pragma unroll
            for (int jp = 0; jp < 2; jp++) {
                uint32_t r0, r1, r2, r3;
                ldmatrix_x4(r0, r1, r2, r3,
                            sb + SVT + swadr((uint32_t)(wn * 32 + jp * 16 + b_rowo), 256, kbyte + b_part));
                bfr[2 * jp][0] = r0; bfr[2 * jp][1] = r1;
                bfr[2 * jp + 1][0] = r2; bfr[2 * jp + 1][1] = r3;
            }
            #pragma unroll
            for (int i = 0; i < 2; i++)
                #pragma unroll
                for (int j = 0; j < 4; j++)
                    mma16816(o[i][j], a[i], bfr[j]);
        }
    }
    __syncthreads();

    // ---- epilogue: write attn2 [ah|al] ----
    #pragma unroll
    for (int i = 0; i < 2; i++) {
        #pragma unroll
        for (int half = 0; half < 2; half++) {
            const int rloc = wm * 32 + i * 16 + half * 8 + (lane >> 2);
            const float inv = 1.0f / lS[rloc];
            const size_t rowg = (size_t)b * Ssz + (size_t)qb * 128 + rloc;
            __half* base = attn2 + rowg * 2048;
            #pragma unroll
            for (int j = 0; j < 4; j++) {
                const int col = h * 64 + wn * 32 + j * 8 + (lane & 3) * 2;
                const float v0 = o[i][j][half * 2] * inv;
                const float v1 = o[i][j][half * 2 + 1] * inv;
                const __half h0 = __float2half_rn(v0);
                const __half h1 = __float2half_rn(v1);
                const __half l0 = __float2half_rn(v0 - __half2float(h0));
                const __half l1 = __float2half_rn(v1 - __half2float(h1));
                *(__half2*)(base + col) = __halves2half2(h0, h1);
                *(__half2*)(base + 1024 + col) = __halves2half2(l0, l1);
            }
        }
    }
}

// ===================== fused residual-add + LayerNorm (+fp16x2 out) ==========
__global__ __launch_bounds__(256)
void add_ln_kernel(const float* __restrict__ A, const float* __restrict__ Bv,
                   const float* __restrict__ g, const float* __restrict__ be,
                   float* __restrict__ Y, __half* __restrict__ Y2)
{
    const int row = blockIdx.x;
    const int tid = threadIdx.x;
    const float4 av = ((const float4*)(A + (size_t)row * Esz))[tid];
    const float4 bv = ((const float4*)(Bv + (size_t)row * Esz))[tid];
    const float v0 = av.x + bv.x, v1 = av.y + bv.y, v2 = av.z + bv.z, v3 = av.w + bv.w;

    float s = v0 + v1 + v2 + v3;
    float s2 = v0 * v0 + v1 * v1 + v2 * v2 + v3 * v3;
    #pragma unroll
    for (int o = 16; o; o >>= 1) {
        s += __shfl_xor_sync(0xffffffffu, s, o);
        s2 += __shfl_xor_sync(0xffffffffu, s2, o);
    }
    __shared__ float ss[8], ss2[8];
    const int w = tid >> 5, ln = tid & 31;
    if (ln == 0) { ss[w] = s; ss2[w] = s2; }
    __syncthreads();
    if (tid < 8) {
        s = ss[tid]; s2 = ss2[tid];
        #pragma unroll
        for (int o = 4; o; o >>= 1) {
            s += __shfl_xor_sync(0x000000ffu, s, o);
            s2 += __shfl_xor_sync(0x000000ffu, s2, o);
        }
        if (tid == 0) { ss[0] = s; ss2[0] = s2; }
    }
    __syncthreads();
    const float mean = ss[0] * (1.0f / Esz);
    const float var = ss2[0] * (1.0f / Esz) - mean * mean;
    const float rstd = rsqrtf(var + 1e-5f);

    const float4 gv = ((const float4*)g)[tid];
    const float4 bev = ((const float4*)be)[tid];
    float4 o4;
    o4.x = (v0 - mean) * rstd * gv.x + bev.x;
    o4.y = (v1 - mean) * rstd * gv.y + bev.y;
    o4.z = (v2 - mean) * rstd * gv.z + bev.z;
    o4.w = (v3 - mean) * rstd * gv.w + bev.w;
    ((float4*)(Y + (size_t)row * Esz))[tid] = o4;

    if (Y2) {
        const float vv[4] = {o4.x, o4.y, o4.z, o4.w};
        __half hh[4], ll[4];
        #pragma unroll
        for (int u = 0; u < 4; u++) {
            hh[u] = __float2half_rn(vv[u]);
            ll[u] = __float2half_rn(vv[u] - __half2float(hh[u]));
        }
        __half* base = Y2 + (size_t)row * 2048 + tid * 4;
        *(__half2*)(base) = __halves2half2(hh[0], hh[1]);
        *(__half2*)(base + 2) = __halves2half2(hh[2], hh[3]);
        *(__half2*)(base + 1024) = __halves2half2(ll[0], ll[1]);
        *(__half2*)(base + 1026) = __halves2half2(ll[2], ll[3]);
    }
}

// ===================== launch ================================================
extern "C" void kernel_launch(void* const* d_in, const int* in_sizes, int n_in,
                              void* d_out, int out_size)
{
    (void)in_sizes; (void)n_in; (void)out_size;
    const float* x     = (const float*)d_in[0];
    const float* w_qkv = (const float*)d_in[1];
    const float* b_qkv = (const float*)d_in[2];
    const float* w_out = (const float*)d_in[3];
    const float* b_out = (const float*)d_in[4];
    const float* g1    = (const float*)d_in[5];
    const float* beta1 = (const float*)d_in[6];
    const float* w_fc1 = (const float*)d_in[7];
    const float* b_fc1 = (const float*)d_in[8];
    const float* w_fc2 = (const float*)d_in[9];
    const float* b_fc2 = (const float*)d_in[10];
    const float* g2    = (const float*)d_in[11];
    const float* beta2 = (const float*)d_in[12];

    float *proj, *x1, *ff;
    cudaGetSymbolAddress((void**)&proj, g_proj);
    cudaGetSymbolAddress((void**)&x1,   g_x1);
    cudaGetSymbolAddress((void**)&ff,   g_ff);
    __half *q2, *k2, *v2t, *attn2, *x2, *x12, *h2, *wq2, *wo2, *w12, *w22;
    cudaGetSymbolAddress((void**)&q2,    g_q2);
    cudaGetSymbolAddress((void**)&k2,    g_k2);
    cudaGetSymbolAddress((void**)&v2t,   g_v2t);
    cudaGetSymbolAddress((void**)&attn2, g_attn2);
    cudaGetSymbolAddress((void**)&x2,    g_x2);
    cudaGetSymbolAddress((void**)&x12,   g_x12);
    cudaGetSymbolAddress((void**)&h2,    g_h2);
    cudaGetSymbolAddress((void**)&wq2,   g_wqkv2);
    cudaGetSymbolAddress((void**)&wo2,   g_wout2);
    cudaGetSymbolAddress((void**)&w12,   g_wfc12);
    cudaGetSymbolAddress((void**)&w22,   g_wfc22);

    cudaFuncSetAttribute(flash_mma_kernel, cudaFuncAttributeMaxDynamicSharedMemorySize, AT_SMEM);
    cudaFuncSetAttribute(gemm_mma_kernel<0>, cudaFuncAttributeMaxDynamicSharedMemorySize, GEMM_SMEM);
    cudaFuncSetAttribute(gemm_mma_kernel<1>, cudaFuncAttributeMaxDynamicSharedMemorySize, GEMM_SMEM);
    cudaFuncSetAttribute(gemm_mma_kernel<2>, cudaFuncAttributeMaxDynamicSharedMemorySize, GEMM_SMEM);

    // weight splits (B-side [hi|hi]); input split (A-side [hi|lo])
    split2_kernel<0><<<3 * Esz, 256>>>(w_qkv, wq2, Esz);
    split2_kernel<0><<<Esz, 256>>>(w_out, wo2, Esz);
    split2_kernel<0><<<FFsz, 256>>>(w_fc1, w12, Esz);
    split2_kernel<0><<<Esz, 256>>>(w_fc2, w22, FFsz);
    split2_kernel<1><<<Msz, 256>>>(x, x2, Esz);

    // 1) qkv = x @ w_qkv^T + b_qkv  -> pre-split q2/k2/v2t
    gemm_mma_kernel<1><<<dim3(3 * Esz / 128, Msz / 128), 256, GEMM_SMEM>>>(
        x2, wq2, b_qkv, nullptr, nullptr, q2, k2, v2t, 3 * Esz, 2 * Esz);
    // 2) attention (fp16 HMMA flash) -> attn2 [ah|al]
    flash_mma_kernel<<<dim3(Ssz / 128, Hsz, Bsz), 256, AT_SMEM>>>(q2, k2, v2t, attn2);
    // 3) proj = attn @ w_out^T + b_out
    gemm_mma_kernel<0><<<dim3(Esz / 128, Msz / 128), 256, GEMM_SMEM>>>(
        attn2, wo2, b_out, proj, nullptr, nullptr, nullptr, nullptr, Esz, 2 * Esz);
    // 4) x1 = LN(x + proj)  (+ x12 fp16x2)
    add_ln_kernel<<<Msz, 256>>>(x, proj, g1, beta1, x1, x12);
    // 5) h2 = fp16x2(gelu(x1 @ w_fc1^T + b_fc1))
    gemm_mma_kernel<2><<<dim3(FFsz / 128, Msz / 128), 256, GEMM_SMEM>>>(
        x12, w12, b_fc1, nullptr, h2, nullptr, nullptr, nullptr, FFsz, 2 * Esz);
    // 6) ff = h @ w_fc2^T + b_fc2
    gemm_mma_kernel<0><<<dim3(Esz / 128, Msz / 128), 256, GEMM_SMEM>>>(
        h2, w22, b_fc2, ff, nullptr, nullptr, nullptr, nullptr, Esz, 2 * FFsz);
    // 7) out = LN(x1 + ff)
    add_ln_kernel<<<Msz, 256>>>(x1, ff, g2, beta2, (float*)d_out, nullptr);
}

// round 6
// speedup vs baseline: 4.6778x; 1.1462x over previous
#include <cuda_runtime.h>
#include <cuda_fp16.h>
#include <math.h>
#include <stdint.h>

// Problem dims (fixed by the reference)
#define Bsz 2
#define Ssz 2048
#define Esz 1024
#define Hsz 16
#define Dsz 64
#define FFsz 4096
#define Msz (Bsz*Ssz)   // 4096 tokens

// ===================== helpers ===============================================
__device__ __forceinline__ uint32_t smem_to_u32(const void* p) {
    uint32_t a;
    asm("{ .reg .u64 t; cvta.to.shared.u64 t, %1; cvt.u32.u64 %0, t; }" : "=r"(a) : "l"(p));
    return a;
}
#define CPASYNC16(saddr, gptr) \
    asm volatile("cp.async.cg.shared.global [%0], [%1], 16;" :: "r"((uint32_t)(saddr)), "l"(gptr))
#define CPASYNC_COMMIT() asm volatile("cp.async.commit_group;" ::: "memory")
#define CPASYNC_WAIT2() asm volatile("cp.async.wait_group 2;" ::: "memory")
#define CPASYNC_WAIT0() asm volatile("cp.async.wait_group 0;" ::: "memory")

__device__ __forceinline__ void ldmatrix_x4(uint32_t& r0, uint32_t& r1, uint32_t& r2, uint32_t& r3,
                                            uint32_t addr) {
    asm volatile("ldmatrix.sync.aligned.m8n8.x4.shared.b16 {%0,%1,%2,%3}, [%4];"
        : "=r"(r0), "=r"(r1), "=r"(r2), "=r"(r3) : "r"(addr));
}
__device__ __forceinline__ void mma16816(float* d, const uint32_t* a, const uint32_t* b) {
    asm volatile("mma.sync.aligned.m16n8k16.row.col.f32.f16.f16.f32 "
        "{%0,%1,%2,%3}, {%4,%5,%6,%7}, {%8,%9}, {%0,%1,%2,%3};"
        : "+f"(d[0]), "+f"(d[1]), "+f"(d[2]), "+f"(d[3])
        : "r"(a[0]), "r"(a[1]), "r"(a[2]), "r"(a[3]), "r"(b[0]), "r"(b[1]));
}
__device__ __forceinline__ uint32_t pkh(__half a, __half b) {
    __half2 t = __halves2half2(a, b);
    return *(uint32_t*)&t;
}
__device__ __forceinline__ void sts32(uint32_t addr, uint32_t v) {
    asm volatile("st.shared.b32 [%0], %1;" :: "r"(addr), "r"(v) : "memory");
}
// swizzled address: row-major, row bytes rb (multiple of 128), XOR within 128B blocks
__device__ __forceinline__ uint32_t swadr(uint32_t row, uint32_t rb, uint32_t c) {
    return row * rb + (c & ~127u) + ((c & 127u) ^ ((row & 7u) * 16u));
}

// ===================== scratch (device globals) ==============================
__device__ float g_proj[(size_t)Msz * Esz];
__device__ float g_x1[(size_t)Msz * Esz];
__device__ float g_ff[(size_t)Msz * Esz];
__device__ __half g_q2[(size_t)Msz * 2 * Esz];        // [tok][h][qh(64)|ql(64)]
__device__ __half g_k2[(size_t)Msz * Esz];            // [tok][h][kh(64)]
__device__ __half g_vt[(size_t)Bsz * Hsz * 64 * Ssz]; // [b,h,d,s] vh plain
__device__ __half g_attn2[(size_t)Msz * Esz];         // hi only
__device__ __half g_x2[(size_t)Msz * 2 * Esz];        // [hi|lo]
__device__ __half g_x12[(size_t)Msz * 2 * Esz];       // [hi|lo]
__device__ __half g_h2[(size_t)Msz * FFsz];           // hi only
__device__ __half g_wqkv2[(size_t)(3 * Esz) * 2 * Esz];  // dup [hi|hi]
__device__ __half g_wout2[(size_t)Esz * Esz];            // plain
__device__ __half g_wfc12[(size_t)FFsz * 2 * Esz];       // dup
__device__ __half g_wfc22[(size_t)Esz * FFsz];           // plain

// ===================== fp16 split/convert ====================================
// TYPE 0: dup [hi|hi] (2K). TYPE 1: [hi|lo] (2K). TYPE 2: plain hi (K).
template<int TYPE>
__global__ __launch_bounds__(256)
void split2_kernel(const float* __restrict__ src, __half* __restrict__ dst, int K)
{
    const int row = blockIdx.x;
    const float* s = src + (size_t)row * K;
    __half* d = dst + (size_t)row * ((TYPE == 2) ? K : 2 * K);
    for (int k = threadIdx.x; k < K; k += 256) {
        const float x = s[k];
        const __half h = __float2half_rn(x);
        d[k] = h;
        if (TYPE == 0) d[K + k] = h;
        if (TYPE == 1) d[K + k] = __float2half_rn(x - __half2float(h));
    }
}

// ===================== HMMA fp16 GEMM (128x256 tile, 512 threads) ============
// C[Msz,N] = A[Msz,K2]*B[N,K2]^T + bias.  lda/ldb = row strides (elements).
// MODE 0: fp32 out C. MODE 1: qkv split epilogue. MODE 2: GELU + fp16 hi out.
#define NBUF 3
#define A_STAGE 16384
#define B_STAGE 32768
#define STAGE_AB (A_STAGE + B_STAGE)
#define GEMM_SMEM (NBUF * STAGE_AB)

template<int MODE>
__global__ __launch_bounds__(512)
void gemm_mma_kernel(const __half* __restrict__ A, const __half* __restrict__ Bm,
                     const float* __restrict__ bias, float* __restrict__ C,
                     __half* __restrict__ C3,
                     __half* __restrict__ q2p, __half* __restrict__ k2p, __half* __restrict__ vtp,
                     int N, int K2, int lda, int ldb)
{
    extern __shared__ __align__(1024) char smem[];
    const uint32_t sbase = smem_to_u32(smem);
    const int tid = threadIdx.x;
    const int lane = tid & 31;
    const int wid = tid >> 5;
    const int wm = wid & 3;        // 4 m-warps (32 rows each)
    const int wn = wid >> 2;       // 4 n-warps (64 cols each)
    const int bx = blockIdx.x, by = blockIdx.y;

    // fill patterns: A 2 chunks/thread (1024 total), B 4 chunks/thread (2048)
    uint32_t stA[2], stB[4];
    const char* Agp[2];
    const char* Bgp[4];
    #pragma unroll
    for (int t = 0; t < 2; t++) {
        const int idx = tid + t * 512;
        const int row = idx >> 3, c = (idx & 7) * 16;
        stA[t] = (uint32_t)(row * 128 + (c ^ ((row & 7) * 16)));
        Agp[t] = (const char*)A + ((size_t)(by * 128 + row) * lda + (idx & 7) * 8) * 2;
    }
    #pragma unroll
    for (int t = 0; t < 4; t++) {
        const int idx = tid + t * 512;
        const int row = idx >> 3, c = (idx & 7) * 16;
        stB[t] = (uint32_t)(row * 128 + (c ^ ((row & 7) * 16)));
        Bgp[t] = (const char*)Bm + ((size_t)(bx * 256 + row) * ldb + (idx & 7) * 8) * 2;
    }

    const uint32_t colxor = (uint32_t)((lane & 7) * 16);
    const uint32_t a_rowbase = (uint32_t)((wm * 32 + (lane & 15)) * 128);
    const uint32_t a_part = (uint32_t)((lane >> 4) * 16);
    const uint32_t b_rowbase = (uint32_t)((wn * 64 + ((lane >> 4) << 3) + (lane & 7)) * 128);
    const uint32_t b_part = (uint32_t)(((lane >> 3) & 1) * 16);

    float acc[2][8][4];
    #pragma unroll
    for (int i = 0; i < 2; i++)
        #pragma unroll
        for (int j = 0; j < 8; j++)
            #pragma unroll
            for (int u = 0; u < 4; u++) acc[i][j][u] = 0.0f;

    const int S = K2 / 64;

    #pragma unroll
    for (int p = 0; p < NBUF; p++) {
        const uint32_t ab = sbase + p * STAGE_AB;
        const uint32_t bb = ab + A_STAGE;
        #pragma unroll
        for (int t = 0; t < 2; t++) CPASYNC16(ab + stA[t], Agp[t] + (size_t)p * 128);
        #pragma unroll
        for (int t = 0; t < 4; t++) CPASYNC16(bb + stB[t], Bgp[t] + (size_t)p * 128);
        CPASYNC_COMMIT();
    }

    #pragma unroll 1
    for (int s = 0; s < S; s++) {
        CPASYNC_WAIT2();
        __syncthreads();
        const uint32_t ab = sbase + (s % NBUF) * STAGE_AB;
        const uint32_t bb = ab + A_STAGE;

        #pragma unroll
        for (int k = 0; k < 4; k++) {
            const uint32_t kb = (uint32_t)(k * 32);
            uint32_t a[2][4], b[8][2];
            #pragma unroll
            for (int i = 0; i < 2; i++)
                ldmatrix_x4(a[i][0], a[i][1], a[i][2], a[i][3],
                            ab + a_rowbase + (uint32_t)(i * 2048) + ((kb + a_part) ^ colxor));
            #pragma unroll
            for (int jp = 0; jp < 4; jp++) {
                uint32_t r0, r1, r2, r3;
                ldmatrix_x4(r0, r1, r2, r3,
                            bb + b_rowbase + (uint32_t)(jp * 2048) + ((kb + b_part) ^ colxor));
                b[2 * jp][0] = r0; b[2 * jp][1] = r1;
                b[2 * jp + 1][0] = r2; b[2 * jp + 1][1] = r3;
            }
            #pragma unroll
            for (int i = 0; i < 2; i++)
                #pragma unroll
                for (int j = 0; j < 8; j++)
                    mma16816(acc[i][j], a[i], b[j]);
        }
        __syncthreads();
        if (s + NBUF < S) {
            const int sn = s + NBUF;
            #pragma unroll
            for (int t = 0; t < 2; t++) CPASYNC16(ab + stA[t], Agp[t] + (size_t)sn * 128);
            #pragma unroll
            for (int t = 0; t < 4; t++) CPASYNC16(bb + stB[t], Bgp[t] + (size_t)sn * 128);
            CPASYNC_COMMIT();
        } else {
            CPASYNC_COMMIT();  // keep wait_group accounting exact
        }
    }

    // ---- epilogue ----
    const int row0 = by * 128 + wm * 32 + (lane >> 2);
    const int col0 = bx * 256 + wn * 64 + (lane & 3) * 2;
    #pragma unroll
    for (int j = 0; j < 8; j++) {
        const int col = col0 + j * 8;
        const float2 bv = *(const float2*)&bias[col];
        #pragma unroll
        for (int i = 0; i < 2; i++) {
            #pragma unroll
            for (int half = 0; half < 2; half++) {
                const int row = row0 + i * 16 + half * 8;
                float v0 = acc[i][j][half * 2 + 0] + bv.x;
                float v1 = acc[i][j][half * 2 + 1] + bv.y;
                if (MODE == 0) {
                    *(float2*)(C + (size_t)row * N + col) = make_float2(v0, v1);
                } else if (MODE == 2) {
                    v0 = 0.5f * v0 * (1.0f + erff(v0 * 0.70710678118654752f));
                    v1 = 0.5f * v1 * (1.0f + erff(v1 * 0.70710678118654752f));
                    *(__half2*)(C3 + (size_t)row * N + col) =
                        __halves2half2(__float2half_rn(v0), __float2half_rn(v1));
                } else {  // MODE 1: qkv split epilogue
                    const int brow = row >> 11;
                    const int srow = row & 2047;
                    const int sec = col >> 10;
                    const int within = col & 1023;
                    const int hh = within >> 6;
                    const int dd = within & 63;
                    const __half h0 = __float2half_rn(v0);
                    const __half h1 = __float2half_rn(v1);
                    if (sec == 0) {
                        const __half l0 = __float2half_rn(v0 - __half2float(h0));
                        const __half l1 = __float2half_rn(v1 - __half2float(h1));
                        __half* qb_ = q2p + (size_t)row * 2048 + hh * 128 + dd;
                        *(__half2*)(qb_) = __halves2half2(h0, h1);
                        *(__half2*)(qb_ + 64) = __halves2half2(l0, l1);
                    } else if (sec == 1) {
                        *(__half2*)(k2p + (size_t)row * 1024 + hh * 64 + dd) = __halves2half2(h0, h1);
                    } else {
                        __half* vb_ = vtp + ((size_t)(brow * Hsz + hh) * 64 + dd) * Ssz + srow;
                        *vb_ = h0;
                        *(vb_ + Ssz) = h1;
                    }
                }
            }
        }
    }
}

// ===================== HMMA flash attention (fp16) ===========================
// grid (S/128, H, B), 256 threads (8 warps: 4 m x 2 n).
// S = [qh|ql] K-dup (8 k-steps).  PV = P (plain) x Vt-hi (4 k-steps).
// K tile for kb+1 prefetched right after S-phase.
#define SQ2 0
#define SK2 32768
#define SVT 49152               // 8KB  (64 d-rows x 128B)
#define SPS 57344               // 16KB (128 rows x 128B)
#define SST 73728
#define AT_SMEM (SST + 4096)

__global__ __launch_bounds__(256)
void flash_mma_kernel(const __half* __restrict__ q2, const __half* __restrict__ k2,
                      const __half* __restrict__ vt, __half* __restrict__ attn2)
{
    extern __shared__ __align__(1024) char sm_[];
    const uint32_t sb = smem_to_u32(sm_);
    float* mS  = (float*)(sm_ + SST);
    float* lS  = mS + 128;
    float* cS  = mS + 256;
    float* rmx = mS + 384;   // [2][128]
    float* rsm = mS + 640;   // [2][128]

    const int tid = threadIdx.x, lane = tid & 31, wid = tid >> 5;
    const int wm = wid & 3, wn = wid >> 2;
    const int qb = blockIdx.x, h = blockIdx.y, b = blockIdx.z;

    const char* qsrc = (const char*)q2 + ((size_t)(b * Ssz + qb * 128) * 2048 + h * 128) * 2;
    const char* ksrc = (const char*)k2 + ((size_t)b * Ssz * 1024 + h * 64) * 2;
    const char* vsrc = (const char*)vt + ((size_t)(b * Hsz + h) * 64) * Ssz * 2;

    // ---- Q fill (cp.async): 128 rows x 256B ----
    #pragma unroll
    for (int it = 0; it < 8; it++) {
        const int idx = tid + it * 256;
        const int r = idx >> 4;
        const int c = (idx & 15) * 16;
        CPASYNC16(sb + SQ2 + swadr(r, 256, c), qsrc + (size_t)r * 4096 + c);
    }
    // ---- K(0) fill duplicated [kh|kh]: 64 rows x 256B ----
    #pragma unroll
    for (int it = 0; it < 2; it++) {
        const int idx = tid + it * 256;
        const int j = idx >> 3;
        const int c = (idx & 7) * 16;
        const char* src = ksrc + (size_t)j * 2048 + c;
        CPASYNC16(sb + SK2 + swadr(j, 256, c), src);
        CPASYNC16(sb + SK2 + swadr(j, 256, 128 + c), src);
    }
    CPASYNC_COMMIT();
    if (tid < 128) { mS[tid] = -INFINITY; lS[tid] = 0.0f; }

    const int a_row = lane & 15;
    const int a_part = (lane >> 4) * 16;
    const int b_rowo = ((lane >> 4) << 3) + (lane & 7);
    const int b_part = ((lane >> 3) & 1) * 16;

    float o[2][4][4];
    #pragma unroll
    for (int i = 0; i < 2; i++)
        #pragma unroll
        for (int j = 0; j < 4; j++)
            #pragma unroll
            for (int u = 0; u < 4; u++) o[i][j][u] = 0.0f;

    #pragma unroll 1
    for (int kb = 0; kb < Ssz / 64; kb++) {
        __syncthreads();  // VT/PS reuse guard (all warps past previous PV)
        // ---- Vt fill: 64 d-rows x 128B (vh for tokens kb*64..) ----
        #pragma unroll
        for (int it = 0; it < 2; it++) {
            const int idx = tid + it * 256;
            const int d = idx >> 3;
            const int c = (idx & 7) * 16;
            CPASYNC16(sb + SVT + swadr(d, 128, c), vsrc + (size_t)d * 4096 + kb * 128 + c);
        }
        CPASYNC_COMMIT();
        CPASYNC_WAIT0();   // waits VT(kb) and K(kb) (prefetched) [+Q on kb=0]
        __syncthreads();

        // ---- S = Q K^T (8 k-steps), warp tile 32x32 ----
        float s[2][4][4];
        #pragma unroll
        for (int i = 0; i < 2; i++)
            #pragma unroll
            for (int j = 0; j < 4; j++)
                #pragma unroll
                for (int u = 0; u < 4; u++) s[i][j][u] = 0.0f;

        #pragma unroll
        for (int ks = 0; ks < 8; ks++) {
            const uint32_t kbyte = (uint32_t)(ks * 32);
            uint32_t a[2][4], bfr[4][2];
            #pragma unroll
            for (int i = 0; i < 2; i++)
                ldmatrix_x4(a[i][0], a[i][1], a[i][2], a[i][3],
                            sb + SQ2 + swadr((uint32_t)(wm * 32 + i * 16 + a_row), 256, kbyte + a_part));
            #pragma unroll
            for (int jp = 0; jp < 2; jp++) {
                uint32_t r0, r1, r2, r3;
                ldmatrix_x4(r0, r1, r2, r3,
                            sb + SK2 + swadr((uint32_t)(wn * 32 + jp * 16 + b_rowo), 256, kbyte + b_part));
                bfr[2 * jp][0] = r0; bfr[2 * jp][1] = r1;
                bfr[2 * jp + 1][0] = r2; bfr[2 * jp + 1][1] = r3;
            }
            #pragma unroll
            for (int i = 0; i < 2; i++)
                #pragma unroll
                for (int j = 0; j < 4; j++)
                    mma16816(s[i][j], a[i], bfr[j]);
        }

        // ---- scale + per-row max ----
        #pragma unroll
        for (int i = 0; i < 2; i++)
            #pragma unroll
            for (int j = 0; j < 4; j++)
                #pragma unroll
                for (int u = 0; u < 4; u++) s[i][j][u] *= 0.125f;

        #pragma unroll
        for (int i = 0; i < 2; i++) {
            #pragma unroll
            for (int half = 0; half < 2; half++) {
                float v = -INFINITY;
                #pragma unroll
                for (int j = 0; j < 4; j++)
                    v = fmaxf(v, fmaxf(s[i][j][half * 2], s[i][j][half * 2 + 1]));
                v = fmaxf(v, __shfl_xor_sync(0xffffffffu, v, 1));
                v = fmaxf(v, __shfl_xor_sync(0xffffffffu, v, 2));
                if ((lane & 3) == 0)
                    rmx[wn * 128 + wm * 32 + i * 16 + half * 8 + (lane >> 2)] = v;
            }
        }
        __syncthreads();   // all warps done with K2 (S-phase complete)

        // ---- early K(kb+1) prefetch into K2 (overlaps softmax + PV) ----
        if (kb + 1 < Ssz / 64) {
            #pragma unroll
            for (int it = 0; it < 2; it++) {
                const int idx = tid + it * 256;
                const int j = idx >> 3;
                const int c = (idx & 7) * 16;
                const char* src = ksrc + (size_t)((kb + 1) * 64 + j) * 2048 + c;
                CPASYNC16(sb + SK2 + swadr(j, 256, c), src);
                CPASYNC16(sb + SK2 + swadr(j, 256, 128 + c), src);
            }
        }
        CPASYNC_COMMIT();

        if (tid < 128) {
            const float mo = mS[tid];
            const float mn = fmaxf(mo, fmaxf(rmx[tid], rmx[128 + tid]));
            mS[tid] = mn;
            cS[tid] = __expf(mo - mn);
        }
        __syncthreads();

        // ---- exp, o-rescale, Ps store (plain fp16), partial sums ----
        #pragma unroll
        for (int i = 0; i < 2; i++) {
            #pragma unroll
            for (int half = 0; half < 2; half++) {
                const int rloc = wm * 32 + i * 16 + half * 8 + (lane >> 2);
                const float mn = mS[rloc];
                const float corr = cS[rloc];
                float rs = 0.0f;
                #pragma unroll
                for (int j = 0; j < 4; j++) {
                    const float p0 = __expf(s[i][j][half * 2] - mn);
                    const float p1 = __expf(s[i][j][half * 2 + 1] - mn);
                    rs += p0 + p1;
                    o[i][j][half * 2] *= corr;
                    o[i][j][half * 2 + 1] *= corr;
                    const uint32_t col = (uint32_t)(wn * 32 + j * 8 + (lane & 3) * 2);
                    sts32(sb + SPS + swadr((uint32_t)rloc, 128, 2 * col),
                          pkh(__float2half_rn(p0), __float2half_rn(p1)));
                }
                rs += __shfl_xor_sync(0xffffffffu, rs, 1);
                rs += __shfl_xor_sync(0xffffffffu, rs, 2);
                if ((lane & 3) == 0)
                    rsm[wn * 128 + rloc] = rs;
            }
        }
        __syncthreads();
        if (tid < 128)
            lS[tid] = lS[tid] * cS[tid] + rsm[tid] + rsm[128 + tid];

        // ---- O += P * Vt^T (4 k-steps), warp tile 32(m)x32(d) ----
        #pragma unroll
        for (int ks = 0; ks < 4; ks++) {
            const uint32_t kbyte = (uint32_t)(ks * 32);
            uint32_t a[2][4], bfr[4][2];
            #pragma unroll
            for (int i = 0; i < 2; i++)
                ldmatrix_x4(a[i][0], a[i][1], a[i][2], a[i][3],
                            sb + SPS + swadr((uint32_t)(wm * 32 + i * 16 + a_row), 128, kbyte + a_part));
            #pragma unroll
            for (int jp = 0; jp < 2; jp++) {
                uint32_t r0, r1, r2, r3;
                ldmatrix_x4(r0, r1, r2, r3,
                            sb + SVT + swadr((uint32_t)(wn * 32 + jp * 16 + b_rowo), 128, kbyte + b_part));
                bfr[2 * jp][0] = r0; bfr[2 * jp][1] = r1;
                bfr[2 * jp + 1][0] = r2; bfr[2 * jp + 1][1] = r3;
            }
            #pragma unroll
            for (int i = 0; i < 2; i++)
                #pragma unroll
                for (int j = 0; j < 4; j++)
                    mma16816(o[i][j], a[i], bfr[j]);
        }
    }
    __syncthreads();

    // ---- epilogue: write attn2 (hi only) ----
    #pragma unroll
    for (int i = 0; i < 2; i++) {
        #pragma unroll
        for (int half = 0; half < 2; half++) {
            const int rloc = wm * 32 + i * 16 + half * 8 + (lane >> 2);
            const float inv = 1.0f / lS[rloc];
            const size_t rowg = (size_t)b * Ssz + (size_t)qb * 128 + rloc;
            __half* base = attn2 + rowg * 1024;
            #pragma unroll
            for (int j = 0; j < 4; j++) {
                const int col = h * 64 + wn * 32 + j * 8 + (lane & 3) * 2;
                *(__half2*)(base + col) = __halves2half2(
                    __float2half_rn(o[i][j][half * 2] * inv),
                    __float2half_rn(o[i][j][half * 2 + 1] * inv));
            }
        }
    }
}

// ===================== fused residual-add + LayerNorm (+fp16x2 out) ==========
__global__ __launch_bounds__(256)
void add_ln_kernel(const float* __restrict__ A, const float* __restrict__ Bv,
                   const float* __restrict__ g, const float* __restrict__ be,
                   float* __restrict__ Y, __half* __restrict__ Y2)
{
    const int row = blockIdx.x;
    const int tid = threadIdx.x;
    const float4 av = ((const float4*)(A + (size_t)row * Esz))[tid];
    const float4 bv = ((const float4*)(Bv + (size_t)row * Esz))[tid];
    const float v0 = av.x + bv.x, v1 = av.y + bv.y, v2 = av.z + bv.z, v3 = av.w + bv.w;

    float s = v0 + v1 + v2 + v3;
    float s2 = v0 * v0 + v1 * v1 + v2 * v2 + v3 * v3;
    #pragma unroll
    for (int o = 16; o; o >>= 1) {
        s += __shfl_xor_sync(0xffffffffu, s, o);
        s2 += __shfl_xor_sync(0xffffffffu, s2, o);
    }
    __shared__ float ss[8], ss2[8];
    const int w = tid >> 5, ln = tid & 31;
    if (ln == 0) { ss[w] = s; ss2[w] = s2; }
    __syncthreads();
    if (tid < 8) {
        s = ss[tid]; s2 = ss2[tid];
        #pragma unroll
        for (int o = 4; o; o >>= 1) {
            s += __shfl_xor_sync(0x000000ffu, s, o);
            s2 += __shfl_xor_sync(0x000000ffu, s2, o);
        }
        if (tid == 0) { ss[0] = s; ss2[0] = s2; }
    }
    __syncthreads();
    const float mean = ss[0] * (1.0f / Esz);
    const float var = ss2[0] * (1.0f / Esz) - mean * mean;
    const float rstd = rsqrtf(var + 1e-5f);

    const float4 gv = ((const float4*)g)[tid];
    const float4 bev = ((const float4*)be)[tid];
    float4 o4;
    o4.x = (v0 - mean) * rstd * gv.x + bev.x;
    o4.y = (v1 - mean) * rstd * gv.y + bev.y;
    o4.z = (v2 - mean) * rstd * gv.z + bev.z;
    o4.w = (v3 - mean) * rstd * gv.w + bev.w;
    ((float4*)(Y + (size_t)row * Esz))[tid] = o4;

    if (Y2) {
        const float vv[4] = {o4.x, o4.y, o4.z, o4.w};
        __half hh[4], ll[4];
        #pragma unroll
        for (int u = 0; u < 4; u++) {
            hh[u] = __float2half_rn(vv[u]);
            ll[u] = __float2half_rn(vv[u] - __half2float(hh[u]));
        }
        __half* base = Y2 + (size_t)row * 2048 + tid * 4;
        *(__half2*)(base) = __halves2half2(hh[0], hh[1]);
        *(__half2*)(base + 2) = __halves2half2(hh[2], hh[3]);
        *(__half2*)(base + 1024) = __halves2half2(ll[0], ll[1]);
        *(__half2*)(base + 1026) = __halves2half2(ll[2], ll[3]);
    }
}

// ===================== launch ================================================
extern "C" void kernel_launch(void* const* d_in, const int* in_sizes, int n_in,
                              void* d_out, int out_size)
{
    (void)in_sizes; (void)n_in; (void)out_size;
    const float* x     = (const float*)d_in[0];
    const float* w_qkv = (const float*)d_in[1];
    const float* b_qkv = (const float*)d_in[2];
    const float* w_out = (const float*)d_in[3];
    const float* b_out = (const float*)d_in[4];
    const float* g1    = (const float*)d_in[5];
    const float* beta1 = (const float*)d_in[6];
    const float* w_fc1 = (const float*)d_in[7];
    const float* b_fc1 = (const float*)d_in[8];
    const float* w_fc2 = (const float*)d_in[9];
    const float* b_fc2 = (const float*)d_in[10];
    const float* g2    = (const float*)d_in[11];
    const float* beta2 = (const float*)d_in[12];

    float *proj, *x1, *ff;
    cudaGetSymbolAddress((void**)&proj, g_proj);
    cudaGetSymbolAddress((void**)&x1,   g_x1);
    cudaGetSymbolAddress((void**)&ff,   g_ff);
    __half *q2, *k2, *vt, *attn2, *x2, *x12, *h2, *wq2, *wo2, *w12, *w22;
    cudaGetSymbolAddress((void**)&q2,    g_q2);
    cudaGetSymbolAddress((void**)&k2,    g_k2);
    cudaGetSymbolAddress((void**)&vt,    g_vt);
    cudaGetSymbolAddress((void**)&attn2, g_attn2);
    cudaGetSymbolAddress((void**)&x2,    g_x2);
    cudaGetSymbolAddress((void**)&x12,   g_x12);
    cudaGetSymbolAddress((void**)&h2,    g_h2);
    cudaGetSymbolAddress((void**)&wq2,   g_wqkv2);
    cudaGetSymbolAddress((void**)&wo2,   g_wout2);
    cudaGetSymbolAddress((void**)&w12,   g_wfc12);
    cudaGetSymbolAddress((void**)&w22,   g_wfc22);

    cudaFuncSetAttribute(flash_mma_kernel, cudaFuncAttributeMaxDynamicSharedMemorySize, AT_SMEM);
    cudaFuncSetAttribute(gemm_mma_kernel<0>, cudaFuncAttributeMaxDynamicSharedMemorySize, GEMM_SMEM);
    cudaFuncSetAttribute(gemm_mma_kernel<1>, cudaFuncAttributeMaxDynamicSharedMemorySize, GEMM_SMEM);
    cudaFuncSetAttribute(gemm_mma_kernel<2>, cudaFuncAttributeMaxDynamicSharedMemorySize, GEMM_SMEM);

    // weight converts: qkv/fc1 dup [hi|hi]; out/fc2 plain. input x: [hi|lo].
    split2_kernel<0><<<3 * Esz, 256>>>(w_qkv, wq2, Esz);
    split2_kernel<2><<<Esz, 256>>>(w_out, wo2, Esz);
    split2_kernel<0><<<FFsz, 256>>>(w_fc1, w12, Esz);
    split2_kernel<2><<<Esz, 256>>>(w_fc2, w22, FFsz);
    split2_kernel<1><<<Msz, 256>>>(x, x2, Esz);

    // 1) qkv = x @ w_qkv^T + b_qkv  -> pre-split q2/k2/vt
    gemm_mma_kernel<1><<<dim3(3 * Esz / 256, Msz / 128), 512, GEMM_SMEM>>>(
        x2, wq2, b_qkv, nullptr, nullptr, q2, k2, vt, 3 * Esz, 2 * Esz, 2 * Esz, 2 * Esz);
    // 2) attention -> attn2 (hi)
    flash_mma_kernel<<<dim3(Ssz / 128, Hsz, Bsz), 256, AT_SMEM>>>(q2, k2, vt, attn2);
    // 3) proj = attn @ w_out^T + b_out   (A hi-only, K=1024)
    gemm_mma_kernel<0><<<dim3(Esz / 256, Msz / 128), 512, GEMM_SMEM>>>(
        attn2, wo2, b_out, proj, nullptr, nullptr, nullptr, nullptr, Esz, Esz, Esz, Esz);
    // 4) x1 = LN(x + proj)  (+ x12 [hi|lo])
    add_ln_kernel<<<Msz, 256>>>(x, proj, g1, beta1, x1, x12);
    // 5) h2 = fp16(gelu(x1 @ w_fc1^T + b_fc1))   (x12 [hi|lo] vs w12 dup)
    gemm_mma_kernel<2><<<dim3(FFsz / 256, Msz / 128), 512, GEMM_SMEM>>>(
        x12, w12, b_fc1, nullptr, h2, nullptr, nullptr, nullptr, FFsz, 2 * Esz, 2 * Esz, 2 * Esz);
    // 6) ff = h @ w_fc2^T + b_fc2   (A hi-only, K=4096)
    gemm_mma_kernel<0><<<dim3(Esz / 256, Msz / 128), 512, GEMM_SMEM>>>(
        h2, w22, b_fc2, ff, nullptr, nullptr, nullptr, nullptr, Esz, FFsz, FFsz, FFsz);
    // 7) out = LN(x1 + ff)
    add_ln_kernel<<<Msz, 256>>>(x1, ff, g2, beta2, (float*)d_out, nullptr);
}

// round 7
// speedup vs baseline: 6.4864x; 1.3866x over previous
#include <cuda_runtime.h>
#include <cuda_fp16.h>
#include <math.h>
#include <stdint.h>

// Problem dims (fixed by the reference)
#define Bsz 2
#define Ssz 2048
#define Esz 1024
#define Hsz 16
#define Dsz 64
#define FFsz 4096
#define Msz (Bsz*Ssz)   // 4096 tokens

// ===================== helpers ===============================================
__device__ __forceinline__ uint32_t smem_to_u32(const void* p) {
    uint32_t a;
    asm("{ .reg .u64 t; cvta.to.shared.u64 t, %1; cvt.u32.u64 %0, t; }" : "=r"(a) : "l"(p));
    return a;
}
#define CPASYNC16(saddr, gptr) \
    asm volatile("cp.async.cg.shared.global [%0], [%1], 16;" :: "r"((uint32_t)(saddr)), "l"(gptr))
#define CPASYNC_COMMIT() asm volatile("cp.async.commit_group;" ::: "memory")
#define CPASYNC_WAIT2() asm volatile("cp.async.wait_group 2;" ::: "memory")
#define CPASYNC_WAIT0() asm volatile("cp.async.wait_group 0;" ::: "memory")

__device__ __forceinline__ void ldmatrix_x4(uint32_t& r0, uint32_t& r1, uint32_t& r2, uint32_t& r3,
                                            uint32_t addr) {
    asm volatile("ldmatrix.sync.aligned.m8n8.x4.shared.b16 {%0,%1,%2,%3}, [%4];"
        : "=r"(r0), "=r"(r1), "=r"(r2), "=r"(r3) : "r"(addr));
}
__device__ __forceinline__ void mma16816(float* d, const uint32_t* a, const uint32_t* b) {
    asm volatile("mma.sync.aligned.m16n8k16.row.col.f32.f16.f16.f32 "
        "{%0,%1,%2,%3}, {%4,%5,%6,%7}, {%8,%9}, {%0,%1,%2,%3};"
        : "+f"(d[0]), "+f"(d[1]), "+f"(d[2]), "+f"(d[3])
        : "r"(a[0]), "r"(a[1]), "r"(a[2]), "r"(a[3]), "r"(b[0]), "r"(b[1]));
}
__device__ __forceinline__ uint32_t pkh(__half a, __half b) {
    __half2 t = __halves2half2(a, b);
    return *(uint32_t*)&t;
}
__device__ __forceinline__ void sts32(uint32_t addr, uint32_t v) {
    asm volatile("st.shared.b32 [%0], %1;" :: "r"(addr), "r"(v) : "memory");
}
// swizzled address: row-major, row bytes rb (multiple of 128), XOR within 128B blocks
__device__ __forceinline__ uint32_t swadr(uint32_t row, uint32_t rb, uint32_t c) {
    return row * rb + (c & ~127u) + ((c & 127u) ^ ((row & 7u) * 16u));
}

// ===================== scratch (device globals) ==============================
__device__ float g_proj[(size_t)Msz * Esz];
__device__ float g_x1[(size_t)Msz * Esz];
__device__ float g_ff[(size_t)Msz * Esz];
__device__ __half g_q2[(size_t)Msz * Esz];            // [tok][h][d]
__device__ __half g_k2[(size_t)Msz * Esz];            // [tok][h][d]
__device__ __half g_vt[(size_t)Bsz * Hsz * 64 * Ssz]; // [b,h,d,s]
__device__ __half g_attn2[(size_t)Msz * Esz];
__device__ __half g_x2[(size_t)Msz * Esz];
__device__ __half g_x12[(size_t)Msz * Esz];
__device__ __half g_h2[(size_t)Msz * FFsz];
__device__ __half g_wqkv2[(size_t)(3 * Esz) * Esz];
__device__ __half g_wout2[(size_t)Esz * Esz];
__device__ __half g_wfc12[(size_t)FFsz * Esz];
__device__ __half g_wfc22[(size_t)Esz * FFsz];

// ===================== fp16 convert ==========================================
__global__ __launch_bounds__(256)
void cvt16_kernel(const float* __restrict__ src, __half* __restrict__ dst, int K)
{
    const int row = blockIdx.x;
    const float* s = src + (size_t)row * K;
    __half* d = dst + (size_t)row * K;
    for (int k = threadIdx.x * 2; k < K; k += 512) {
        const float2 f = *(const float2*)(s + k);
        *(__half2*)(d + k) = __halves2half2(__float2half_rn(f.x), __float2half_rn(f.y));
    }
}

// ===================== HMMA fp16 GEMM (128x256 tile, 512 threads) ============
// C[Msz,N] = A[Msz,K]*B[N,K]^T + bias.  lda/ldb = row strides (elements).
// MODE 0: fp32 out C. MODE 1: qkv split epilogue. MODE 2: GELU + fp16 out.
#define NBUF 3
#define A_STAGE 16384
#define B_STAGE 32768
#define STAGE_AB (A_STAGE + B_STAGE)
#define GEMM_SMEM (NBUF * STAGE_AB)

template<int MODE>
__global__ __launch_bounds__(512)
void gemm_mma_kernel(const __half* __restrict__ A, const __half* __restrict__ Bm,
                     const float* __restrict__ bias, float* __restrict__ C,
                     __half* __restrict__ C3,
                     __half* __restrict__ q2p, __half* __restrict__ k2p, __half* __restrict__ vtp,
                     int N, int K2, int lda, int ldb)
{
    extern __shared__ __align__(1024) char smem[];
    const uint32_t sbase = smem_to_u32(smem);
    const int tid = threadIdx.x;
    const int lane = tid & 31;
    const int wid = tid >> 5;
    const int wm = wid & 3;        // 4 m-warps (32 rows each)
    const int wn = wid >> 2;       // 4 n-warps (64 cols each)
    const int bx = blockIdx.x, by = blockIdx.y;

    uint32_t stA[2], stB[4];
    const char* Agp[2];
    const char* Bgp[4];
    #pragma unroll
    for (int t = 0; t < 2; t++) {
        const int idx = tid + t * 512;
        const int row = idx >> 3, c = (idx & 7) * 16;
        stA[t] = (uint32_t)(row * 128 + (c ^ ((row & 7) * 16)));
        Agp[t] = (const char*)A + ((size_t)(by * 128 + row) * lda + (idx & 7) * 8) * 2;
    }
    #pragma unroll
    for (int t = 0; t < 4; t++) {
        const int idx = tid + t * 512;
        const int row = idx >> 3, c = (idx & 7) * 16;
        stB[t] = (uint32_t)(row * 128 + (c ^ ((row & 7) * 16)));
        Bgp[t] = (const char*)Bm + ((size_t)(bx * 256 + row) * ldb + (idx & 7) * 8) * 2;
    }

    const uint32_t colxor = (uint32_t)((lane & 7) * 16);
    const uint32_t a_rowbase = (uint32_t)((wm * 32 + (lane & 15)) * 128);
    const uint32_t a_part = (uint32_t)((lane >> 4) * 16);
    const uint32_t b_rowbase = (uint32_t)((wn * 64 + ((lane >> 4) << 3) + (lane & 7)) * 128);
    const uint32_t b_part = (uint32_t)(((lane >> 3) & 1) * 16);

    float acc[2][8][4];
    #pragma unroll
    for (int i = 0; i < 2; i++)
        #pragma unroll
        for (int j = 0; j < 8; j++)
            #pragma unroll
            for (int u = 0; u < 4; u++) acc[i][j][u] = 0.0f;

    const int S = K2 / 64;

    #pragma unroll
    for (int p = 0; p < NBUF; p++) {
        const uint32_t ab = sbase + p * STAGE_AB;
        const uint32_t bb = ab + A_STAGE;
        #pragma unroll
        for (int t = 0; t < 2; t++) CPASYNC16(ab + stA[t], Agp[t] + (size_t)p * 128);
        #pragma unroll
        for (int t = 0; t < 4; t++) CPASYNC16(bb + stB[t], Bgp[t] + (size_t)p * 128);
        CPASYNC_COMMIT();
    }

    #pragma unroll 1
    for (int s = 0; s < S; s++) {
        CPASYNC_WAIT2();
        __syncthreads();
        const uint32_t ab = sbase + (s % NBUF) * STAGE_AB;
        const uint32_t bb = ab + A_STAGE;

        #pragma unroll
        for (int k = 0; k < 4; k++) {
            const uint32_t kb = (uint32_t)(k * 32);
            uint32_t a[2][4], b[8][2];
            #pragma unroll
            for (int i = 0; i < 2; i++)
                ldmatrix_x4(a[i][0], a[i][1], a[i][2], a[i][3],
                            ab + a_rowbase + (uint32_t)(i * 2048) + ((kb + a_part) ^ colxor));
            #pragma unroll
            for (int jp = 0; jp < 4; jp++) {
                uint32_t r0, r1, r2, r3;
                ldmatrix_x4(r0, r1, r2, r3,
                            bb + b_rowbase + (uint32_t)(jp * 2048) + ((kb + b_part) ^ colxor));
                b[2 * jp][0] = r0; b[2 * jp][1] = r1;
                b[2 * jp + 1][0] = r2; b[2 * jp + 1][1] = r3;
            }
            #pragma unroll
            for (int i = 0; i < 2; i++)
                #pragma unroll
                for (int j = 0; j < 8; j++)
                    mma16816(acc[i][j], a[i], b[j]);
        }
        __syncthreads();
        if (s + NBUF < S) {
            const int sn = s + NBUF;
            #pragma unroll
            for (int t = 0; t < 2; t++) CPASYNC16(ab + stA[t], Agp[t] + (size_t)sn * 128);
            #pragma unroll
            for (int t = 0; t < 4; t++) CPASYNC16(bb + stB[t], Bgp[t] + (size_t)sn * 128);
            CPASYNC_COMMIT();
        } else {
            CPASYNC_COMMIT();  // keep wait_group accounting exact
        }
    }

    // ---- epilogue ----
    const int row0 = by * 128 + wm * 32 + (lane >> 2);
    const int col0 = bx * 256 + wn * 64 + (lane & 3) * 2;
    #pragma unroll
    for (int j = 0; j < 8; j++) {
        const int col = col0 + j * 8;
        const float2 bv = *(const float2*)&bias[col];
        #pragma unroll
        for (int i = 0; i < 2; i++) {
            #pragma unroll
            for (int half = 0; half < 2; half++) {
                const int row = row0 + i * 16 + half * 8;
                float v0 = acc[i][j][half * 2 + 0] + bv.x;
                float v1 = acc[i][j][half * 2 + 1] + bv.y;
                if (MODE == 0) {
                    *(float2*)(C + (size_t)row * N + col) = make_float2(v0, v1);
                } else if (MODE == 2) {
                    v0 = 0.5f * v0 * (1.0f + erff(v0 * 0.70710678118654752f));
                    v1 = 0.5f * v1 * (1.0f + erff(v1 * 0.70710678118654752f));
                    *(__half2*)(C3 + (size_t)row * N + col) =
                        __halves2half2(__float2half_rn(v0), __float2half_rn(v1));
                } else {  // MODE 1: qkv split epilogue
                    const int brow = row >> 11;
                    const int srow = row & 2047;
                    const int sec = col >> 10;
                    const int within = col & 1023;
                    const int hh = within >> 6;
                    const int dd = within & 63;
                    const __half h0 = __float2half_rn(v0);
                    const __half h1 = __float2half_rn(v1);
                    if (sec == 0) {
                        *(__half2*)(q2p + (size_t)row * 1024 + hh * 64 + dd) = __halves2half2(h0, h1);
                    } else if (sec == 1) {
                        *(__half2*)(k2p + (size_t)row * 1024 + hh * 64 + dd) = __halves2half2(h0, h1);
                    } else {
                        __half* vb_ = vtp + ((size_t)(brow * Hsz + hh) * 64 + dd) * Ssz + srow;
                        *vb_ = h0;
                        *(vb_ + Ssz) = h1;
                    }
                }
            }
        }
    }
}

// ===================== HMMA flash attention (pure fp16) ======================
// grid (S/128, H, B), 256 threads (8 warps: 4 m x 2 n).
// S = Q K^T (4 k-steps).  PV = P x Vt (4 k-steps).
// K tile for kb+1 prefetched right after S-phase.
#define SQ2 0                   // 16KB (128 rows x 128B)
#define SK2 16384               // 8KB  (64 rows x 128B)
#define SVT 24576               // 8KB  (64 d-rows x 128B)
#define SPS 32768               // 16KB (128 rows x 128B)
#define SST 49152
#define AT_SMEM (SST + 4096)

__global__ __launch_bounds__(256)
void flash_mma_kernel(const __half* __restrict__ q2, const __half* __restrict__ k2,
                      const __half* __restrict__ vt, __half* __restrict__ attn2)
{
    extern __shared__ __align__(1024) char sm_[];
    const uint32_t sb = smem_to_u32(sm_);
    float* mS  = (float*)(sm_ + SST);
    float* lS  = mS + 128;
    float* cS  = mS + 256;
    float* rmx = mS + 384;   // [2][128]
    float* rsm = mS + 640;   // [2][128]

    const int tid = threadIdx.x, lane = tid & 31, wid = tid >> 5;
    const int wm = wid & 3, wn = wid >> 2;
    const int qb = blockIdx.x, h = blockIdx.y, b = blockIdx.z;

    const char* qsrc = (const char*)q2 + ((size_t)(b * Ssz + qb * 128) * 1024 + h * 64) * 2;
    const char* ksrc = (const char*)k2 + ((size_t)b * Ssz * 1024 + h * 64) * 2;
    const char* vsrc = (const char*)vt + ((size_t)(b * Hsz + h) * 64) * Ssz * 2;

    // ---- Q fill (cp.async): 128 rows x 128B ----
    #pragma unroll
    for (int it = 0; it < 4; it++) {
        const int idx = tid + it * 256;
        const int r = idx >> 3;
        const int c = (idx & 7) * 16;
        CPASYNC16(sb + SQ2 + swadr(r, 128, c), qsrc + (size_t)r * 2048 + c);
    }
    // ---- K(0) fill: 64 rows x 128B ----
    #pragma unroll
    for (int it = 0; it < 2; it++) {
        const int idx = tid + it * 256;
        const int j = idx >> 3;
        const int c = (idx & 7) * 16;
        CPASYNC16(sb + SK2 + swadr(j, 128, c), ksrc + (size_t)j * 2048 + c);
    }
    CPASYNC_COMMIT();
    if (tid < 128) { mS[tid] = -INFINITY; lS[tid] = 0.0f; }

    const int a_row = lane & 15;
    const int a_part = (lane >> 4) * 16;
    const int b_rowo = ((lane >> 4) << 3) + (lane & 7);
    const int b_part = ((lane >> 3) & 1) * 16;

    float o[2][4][4];
    #pragma unroll
    for (int i = 0; i < 2; i++)
        #pragma unroll
        for (int j = 0; j < 4; j++)
            #pragma unroll
            for (int u = 0; u < 4; u++) o[i][j][u] = 0.0f;

    #pragma unroll 1
    for (int kb = 0; kb < Ssz / 64; kb++) {
        __syncthreads();  // VT/PS reuse guard (all warps past previous PV)
        // ---- Vt fill: 64 d-rows x 128B ----
        #pragma unroll
        for (int it = 0; it < 2; it++) {
            const int idx = tid + it * 256;
            const int d = idx >> 3;
            const int c = (idx & 7) * 16;
            CPASYNC16(sb + SVT + swadr(d, 128, c), vsrc + (size_t)d * 4096 + kb * 128 + c);
        }
        CPASYNC_COMMIT();
        CPASYNC_WAIT0();   // waits VT(kb) and K(kb) (prefetched) [+Q on kb=0]
        __syncthreads();

        // ---- S = Q K^T (4 k-steps), warp tile 32x32 ----
        float s[2][4][4];
        #pragma unroll
        for (int i = 0; i < 2; i++)
            #pragma unroll
            for (int j = 0; j < 4; j++)
                #pragma unroll
                for (int u = 0; u < 4; u++) s[i][j][u] = 0.0f;

        #pragma unroll
        for (int ks = 0; ks < 4; ks++) {
            const uint32_t kbyte = (uint32_t)(ks * 32);
            uint32_t a[2][4], bfr[4][2];
            #pragma unroll
            for (int i = 0; i < 2; i++)
                ldmatrix_x4(a[i][0], a[i][1], a[i][2], a[i][3],
                            sb + SQ2 + swadr((uint32_t)(wm * 32 + i * 16 + a_row), 128, kbyte + a_part));
            #pragma unroll
            for (int jp = 0; jp < 2; jp++) {
                uint32_t r0, r1, r2, r3;
                ldmatrix_x4(r0, r1, r2, r3,
                            sb + SK2 + swadr((uint32_t)(wn * 32 + jp * 16 + b_rowo), 128, kbyte + b_part));
                bfr[2 * jp][0] = r0; bfr[2 * jp][1] = r1;
                bfr[2 * jp + 1][0] = r2; bfr[2 * jp + 1][1] = r3;
            }
            #pragma unroll
            for (int i = 0; i < 2; i++)
                #pragma unroll
                for (int j = 0; j < 4; j++)
                    mma16816(s[i][j], a[i], bfr[j]);
        }

        // ---- scale + per-row max ----
        #pragma unroll
        for (int i = 0; i < 2; i++)
            #pragma unroll
            for (int j = 0; j < 4; j++)
                #pragma unroll
                for (int u = 0; u < 4; u++) s[i][j][u] *= 0.125f;

        #pragma unroll
        for (int i = 0; i < 2; i++) {
            #pragma unroll
            for (int half = 0; half < 2; half++) {
                float v = -INFINITY;
                #pragma unroll
                for (int j = 0; j < 4; j++)
                    v = fmaxf(v, fmaxf(s[i][j][half * 2], s[i][j][half * 2 + 1]));
                v = fmaxf(v, __shfl_xor_sync(0xffffffffu, v, 1));
                v = fmaxf(v, __shfl_xor_sync(0xffffffffu, v, 2));
                if ((lane & 3) == 0)
                    rmx[wn * 128 + wm * 32 + i * 16 + half * 8 + (lane >> 2)] = v;
            }
        }
        __syncthreads();   // all warps done with K2 (S-phase complete)

        // ---- early K(kb+1) prefetch into K2 (overlaps softmax + PV) ----
        if (kb + 1 < Ssz / 64) {
            #pragma unroll
            for (int it = 0; it < 2; it++) {
                const int idx = tid + it * 256;
                const int j = idx >> 3;
                const int c = (idx & 7) * 16;
                CPASYNC16(sb + SK2 + swadr(j, 128, c),
                          ksrc + (size_t)((kb + 1) * 64 + j) * 2048 + c);
            }
        }
        CPASYNC_COMMIT();

        if (tid < 128) {
            const float mo = mS[tid];
            const float mn = fmaxf(mo, fmaxf(rmx[tid], rmx[128 + tid]));
            mS[tid] = mn;
            cS[tid] = __expf(mo - mn);
        }
        __syncthreads();

        // ---- exp, o-rescale, Ps store (fp16), partial sums ----
        #pragma unroll
        for (int i = 0; i < 2; i++) {
            #pragma unroll
            for (int half = 0; half < 2; half++) {
                const int rloc = wm * 32 + i * 16 + half * 8 + (lane >> 2);
                const float mn = mS[rloc];
                const float corr = cS[rloc];
                float rs = 0.0f;
                #pragma unroll
                for (int j = 0; j < 4; j++) {
                    const float p0 = __expf(s[i][j][half * 2] - mn);
                    const float p1 = __expf(s[i][j][half * 2 + 1] - mn);
                    rs += p0 + p1;
                    o[i][j][half * 2] *= corr;
                    o[i][j][half * 2 + 1] *= corr;
                    const uint32_t col = (uint32_t)(wn * 32 + j * 8 + (lane & 3) * 2);
                    sts32(sb + SPS + swadr((uint32_t)rloc, 128, 2 * col),
                          pkh(__float2half_rn(p0), __float2half_rn(p1)));
                }
                rs += __shfl_xor_sync(0xffffffffu, rs, 1);
                rs += __shfl_xor_sync(0xffffffffu, rs, 2);
                if ((lane & 3) == 0)
                    rsm[wn * 128 + rloc] = rs;
            }
        }
        __syncthreads();
        if (tid < 128)
            lS[tid] = lS[tid] * cS[tid] + rsm[tid] + rsm[128 + tid];

        // ---- O += P * Vt^T (4 k-steps), warp tile 32(m)x32(d) ----
        #pragma unroll
        for (int ks = 0; ks < 4; ks++) {
            const uint32_t kbyte = (uint32_t)(ks * 32);
            uint32_t a[2][4], bfr[4][2];
            #pragma unroll
            for (int i = 0; i < 2; i++)
                ldmatrix_x4(a[i][0], a[i][1], a[i][2], a[i][3],
                            sb + SPS + swadr((uint32_t)(wm * 32 + i * 16 + a_row), 128, kbyte + a_part));
            #pragma unroll
            for (int jp = 0; jp < 2; jp++) {
                uint32_t r0, r1, r2, r3;
                ldmatrix_x4(r0, r1, r2, r3,
                            sb + SVT + swadr((uint32_t)(wn * 32 + jp * 16 + b_rowo), 128, kbyte + b_part));
                bfr[2 * jp][0] = r0; bfr[2 * jp][1] = r1;
                bfr[2 * jp + 1][0] = r2; bfr[2 * jp + 1][1] = r3;
            }
            #pragma unroll
            for (int i = 0; i < 2; i++)
                #pragma unroll
                for (int j = 0; j < 4; j++)
                    mma16816(o[i][j], a[i], bfr[j]);
        }
    }
    __syncthreads();

    // ---- epilogue: write attn2 ----
    #pragma unroll
    for (int i = 0; i < 2; i++) {
        #pragma unroll
        for (int half = 0; half < 2; half++) {
            const int rloc = wm * 32 + i * 16 + half * 8 + (lane >> 2);
            const float inv = 1.0f / lS[rloc];
            const size_t rowg = (size_t)b * Ssz + (size_t)qb * 128 + rloc;
            __half* base = attn2 + rowg * 1024;
            #pragma unroll
            for (int j = 0; j < 4; j++) {
                const int col = h * 64 + wn * 32 + j * 8 + (lane & 3) * 2;
                *(__half2*)(base + col) = __halves2half2(
                    __float2half_rn(o[i][j][half * 2] * inv),
                    __float2half_rn(o[i][j][half * 2 + 1] * inv));
            }
        }
    }
}

// ===================== fused residual-add + LayerNorm (+fp16 out) ============
__global__ __launch_bounds__(256)
void add_ln_kernel(const float* __restrict__ A, const float* __restrict__ Bv,
                   const float* __restrict__ g, const float* __restrict__ be,
                   float* __restrict__ Y, __half* __restrict__ Y2)
{
    const int row = blockIdx.x;
    const int tid = threadIdx.x;
    const float4 av = ((const float4*)(A + (size_t)row * Esz))[tid];
    const float4 bv = ((const float4*)(Bv + (size_t)row * Esz))[tid];
    const float v0 = av.x + bv.x, v1 = av.y + bv.y, v2 = av.z + bv.z, v3 = av.w + bv.w;

    float s = v0 + v1 + v2 + v3;
    float s2 = v0 * v0 + v1 * v1 + v2 * v2 + v3 * v3;
    #pragma unroll
    for (int o = 16; o; o >>= 1) {
        s += __shfl_xor_sync(0xffffffffu, s, o);
        s2 += __shfl_xor_sync(0xffffffffu, s2, o);
    }
    __shared__ float ss[8], ss2[8];
    const int w = tid >> 5, ln = tid & 31;
    if (ln == 0) { ss[w] = s; ss2[w] = s2; }
    __syncthreads();
    if (tid < 8) {
        s = ss[tid]; s2 = ss2[tid];
        #pragma unroll
        for (int o = 4; o; o >>= 1) {
            s += __shfl_xor_sync(0x000000ffu, s, o);
            s2 += __shfl_xor_sync(0x000000ffu, s2, o);
        }
        if (tid == 0) { ss[0] = s; ss2[0] = s2; }
    }
    __syncthreads();
    const float mean = ss[0] * (1.0f / Esz);
    const float var = ss2[0] * (1.0f / Esz) - mean * mean;
    const float rstd = rsqrtf(var + 1e-5f);

    const float4 gv = ((const float4*)g)[tid];
    const float4 bev = ((const float4*)be)[tid];
    float4 o4;
    o4.x = (v0 - mean) * rstd * gv.x + bev.x;
    o4.y = (v1 - mean) * rstd * gv.y + bev.y;
    o4.z = (v2 - mean) * rstd * gv.z + bev.z;
    o4.w = (v3 - mean) * rstd * gv.w + bev.w;
    ((float4*)(Y + (size_t)row * Esz))[tid] = o4;

    if (Y2) {
        __half* base = Y2 + (size_t)row * 1024 + tid * 4;
        *(__half2*)(base) = __halves2half2(__float2half_rn(o4.x), __float2half_rn(o4.y));
        *(__half2*)(base + 2) = __halves2half2(__float2half_rn(o4.z), __float2half_rn(o4.w));
    }
}

// ===================== launch ================================================
extern "C" void kernel_launch(void* const* d_in, const int* in_sizes, int n_in,
                              void* d_out, int out_size)
{
    (void)in_sizes; (void)n_in; (void)out_size;
    const float* x     = (const float*)d_in[0];
    const float* w_qkv = (const float*)d_in[1];
    const float* b_qkv = (const float*)d_in[2];
    const float* w_out = (const float*)d_in[3];
    const float* b_out = (const float*)d_in[4];
    const float* g1    = (const float*)d_in[5];
    const float* beta1 = (const float*)d_in[6];
    const float* w_fc1 = (const float*)d_in[7];
    const float* b_fc1 = (const float*)d_in[8];
    const float* w_fc2 = (const float*)d_in[9];
    const float* b_fc2 = (const float*)d_in[10];
    const float* g2    = (const float*)d_in[11];
    const float* beta2 = (const float*)d_in[12];

    float *proj, *x1, *ff;
    cudaGetSymbolAddress((void**)&proj, g_proj);
    cudaGetSymbolAddress((void**)&x1,   g_x1);
    cudaGetSymbolAddress((void**)&ff,   g_ff);
    __half *q2, *k2, *vt, *attn2, *x2, *x12, *h2, *wq2, *wo2, *w12, *w22;
    cudaGetSymbolAddress((void**)&q2,    g_q2);
    cudaGetSymbolAddress((void**)&k2,    g_k2);
    cudaGetSymbolAddress((void**)&vt,    g_vt);
    cudaGetSymbolAddress((void**)&attn2, g_attn2);
    cudaGetSymbolAddress((void**)&x2,    g_x2);
    cudaGetSymbolAddress((void**)&x12,   g_x12);
    cudaGetSymbolAddress((void**)&h2,    g_h2);
    cudaGetSymbolAddress((void**)&wq2,   g_wqkv2);
    cudaGetSymbolAddress((void**)&wo2,   g_wout2);
    cudaGetSymbolAddress((void**)&w12,   g_wfc12);
    cudaGetSymbolAddress((void**)&w22,   g_wfc22);

    cudaFuncSetAttribute(flash_mma_kernel, cudaFuncAttributeMaxDynamicSharedMemorySize, AT_SMEM);
    cudaFuncSetAttribute(gemm_mma_kernel<0>, cudaFuncAttributeMaxDynamicSharedMemorySize, GEMM_SMEM);
    cudaFuncSetAttribute(gemm_mma_kernel<1>, cudaFuncAttributeMaxDynamicSharedMemorySize, GEMM_SMEM);
    cudaFuncSetAttribute(gemm_mma_kernel<2>, cudaFuncAttributeMaxDynamicSharedMemorySize, GEMM_SMEM);

    // fp16 converts (all plain)
    cvt16_kernel<<<3 * Esz, 256>>>(w_qkv, wq2, Esz);
    cvt16_kernel<<<Esz, 256>>>(w_out, wo2, Esz);
    cvt16_kernel<<<FFsz, 256>>>(w_fc1, w12, Esz);
    cvt16_kernel<<<Esz, 256>>>(w_fc2, w22, FFsz);
    cvt16_kernel<<<Msz, 256>>>(x, x2, Esz);

    // 1) qkv = x @ w_qkv^T + b_qkv  -> q2/k2/vt
    gemm_mma_kernel<1><<<dim3(3 * Esz / 256, Msz / 128), 512, GEMM_SMEM>>>(
        x2, wq2, b_qkv, nullptr, nullptr, q2, k2, vt, 3 * Esz, Esz, Esz, Esz);
    // 2) attention -> attn2
    flash_mma_kernel<<<dim3(Ssz / 128, Hsz, Bsz), 256, AT_SMEM>>>(q2, k2, vt, attn2);
    // 3) proj = attn @ w_out^T + b_out
    gemm_mma_kernel<0><<<dim3(Esz / 256, Msz / 128), 512, GEMM_SMEM>>>(
        attn2, wo2, b_out, proj, nullptr, nullptr, nullptr, nullptr, Esz, Esz, Esz, Esz);
    // 4) x1 = LN(x + proj)  (+ x12 fp16)
    add_ln_kernel<<<Msz, 256>>>(x, proj, g1, beta1, x1, x12);
    // 5) h2 = fp16(gelu(x1 @ w_fc1^T + b_fc1))
    gemm_mma_kernel<2><<<dim3(FFsz / 256, Msz / 128), 512, GEMM_SMEM>>>(
        x12, w12, b_fc1, nullptr, h2, nullptr, nullptr, nullptr, FFsz, Esz, Esz, Esz);
    // 6) ff = h @ w_fc2^T + b_fc2
    gemm_mma_kernel<0><<<dim3(Esz / 256, Msz / 128), 512, GEMM_SMEM>>>(
        h2, w22, b_fc2, ff, nullptr, nullptr, nullptr, nullptr, Esz, FFsz, FFsz, FFsz);
    // 7) out = LN(x1 + ff)
    add_ln_kernel<<<Msz, 256>>>(x1, ff, g2, beta2, (float*)d_out, nullptr);
}

// round 8
// speedup vs baseline: 7.6971x; 1.1867x over previous
#include <cuda_runtime.h>
#include <cuda_fp16.h>
#include <math.h>
#include <stdint.h>

// Problem dims (fixed by the reference)
#define Bsz 2
#define Ssz 2048
#define Esz 1024
#define Hsz 16
#define Dsz 64
#define FFsz 4096
#define Msz (Bsz*Ssz)   // 4096 tokens

// ===================== helpers ===============================================
__device__ __forceinline__ uint32_t smem_to_u32(const void* p) {
    uint32_t a;
    asm("{ .reg .u64 t; cvta.to.shared.u64 t, %1; cvt.u32.u64 %0, t; }" : "=r"(a) : "l"(p));
    return a;
}
#define CPASYNC16(saddr, gptr) \
    asm volatile("cp.async.cg.shared.global [%0], [%1], 16;" :: "r"((uint32_t)(saddr)), "l"(gptr))
#define CPASYNC_COMMIT() asm volatile("cp.async.commit_group;" ::: "memory")
#define CPASYNC_WAIT2() asm volatile("cp.async.wait_group 2;" ::: "memory")
#define CPASYNC_WAIT1() asm volatile("cp.async.wait_group 1;" ::: "memory")
#define CPASYNC_WAIT0() asm volatile("cp.async.wait_group 0;" ::: "memory")

__device__ __forceinline__ void ldmatrix_x4(uint32_t& r0, uint32_t& r1, uint32_t& r2, uint32_t& r3,
                                            uint32_t addr) {
    asm volatile("ldmatrix.sync.aligned.m8n8.x4.shared.b16 {%0,%1,%2,%3}, [%4];"
        : "=r"(r0), "=r"(r1), "=r"(r2), "=r"(r3) : "r"(addr));
}
__device__ __forceinline__ void mma16816(float* d, const uint32_t* a, const uint32_t* b) {
    asm volatile("mma.sync.aligned.m16n8k16.row.col.f32.f16.f16.f32 "
        "{%0,%1,%2,%3}, {%4,%5,%6,%7}, {%8,%9}, {%0,%1,%2,%3};"
        : "+f"(d[0]), "+f"(d[1]), "+f"(d[2]), "+f"(d[3])
        : "r"(a[0]), "r"(a[1]), "r"(a[2]), "r"(a[3]), "r"(b[0]), "r"(b[1]));
}
__device__ __forceinline__ uint32_t pkh(__half a, __half b) {
    __half2 t = __halves2half2(a, b);
    return *(uint32_t*)&t;
}
// swizzled address: row-major, row bytes rb (multiple of 128), XOR within 128B blocks
__device__ __forceinline__ uint32_t swadr(uint32_t row, uint32_t rb, uint32_t c) {
    return row * rb + (c & ~127u) + ((c & 127u) ^ ((row & 7u) * 16u));
}

// ===================== scratch (device globals) ==============================
__device__ float g_proj[(size_t)Msz * Esz];
__device__ float g_x1[(size_t)Msz * Esz];
__device__ float g_ff[(size_t)Msz * Esz];
__device__ __half g_q2[(size_t)Msz * Esz];            // [tok][h][d]
__device__ __half g_k2[(size_t)Msz * Esz];            // [tok][h][d]
__device__ __half g_vt[(size_t)Bsz * Hsz * 64 * Ssz]; // [b,h,d,s]
__device__ __half g_attn2[(size_t)Msz * Esz];
__device__ __half g_x2[(size_t)Msz * Esz];
__device__ __half g_x12[(size_t)Msz * Esz];
__device__ __half g_h2[(size_t)Msz * FFsz];
__device__ __half g_wqkv2[(size_t)(3 * Esz) * Esz];
__device__ __half g_wout2[(size_t)Esz * Esz];
__device__ __half g_wfc12[(size_t)FFsz * Esz];
__device__ __half g_wfc22[(size_t)Esz * FFsz];

// ===================== fused fp32->fp16 convert (all tensors) ================
__device__ __forceinline__ void cvt_seg(const float* __restrict__ s, __half* __restrict__ d,
                                        int n4, int base, int stride)
{
    for (int i = base; i < n4; i += stride) {
        const float4 f = ((const float4*)s)[i];
        __half* o = d + i * 4;
        *(__half2*)(o)     = __halves2half2(__float2half_rn(f.x), __float2half_rn(f.y));
        *(__half2*)(o + 2) = __halves2half2(__float2half_rn(f.z), __float2half_rn(f.w));
    }
}
__global__ __launch_bounds__(256)
void cvt_all_kernel(const float* w_qkv, const float* w_out, const float* w_fc1,
                    const float* w_fc2, const float* x,
                    __half* wq2, __half* wo2, __half* w12, __half* w22, __half* x2)
{
    const int base = blockIdx.x * 256 + threadIdx.x;
    const int stride = gridDim.x * 256;
    cvt_seg(w_qkv, wq2, (3 * Esz * Esz) / 4, base, stride);
    cvt_seg(w_out, wo2, (Esz * Esz) / 4, base, stride);
    cvt_seg(w_fc1, w12, (FFsz * Esz) / 4, base, stride);
    cvt_seg(w_fc2, w22, (Esz * FFsz) / 4, base, stride);
    cvt_seg(x, x2, (Msz * Esz) / 4, base, stride);
}

// ===================== HMMA fp16 GEMM (128x128 tile, 256 threads, 2 CTA/SM) ==
// C[Msz,N] = A[Msz,K]*B[N,K]^T + bias.  lda/ldb = row strides (elements).
// MODE 0: fp32 out C. MODE 1: qkv split epilogue. MODE 2: GELU + fp16 out.
#define NBUF 3
#define STAGE_BYTES (128 * 128)
#define STAGE_AB (2 * STAGE_BYTES)
#define GEMM_SMEM (NBUF * STAGE_AB)

template<int MODE>
__global__ __launch_bounds__(256, 2)
void gemm_mma_kernel(const __half* __restrict__ A, const __half* __restrict__ Bm,
                     const float* __restrict__ bias, float* __restrict__ C,
                     __half* __restrict__ C3,
                     __half* __restrict__ q2p, __half* __restrict__ k2p, __half* __restrict__ vtp,
                     int N, int K2, int lda, int ldb)
{
    extern __shared__ __align__(1024) char smem[];
    const uint32_t sbase = smem_to_u32(smem);
    const int tid = threadIdx.x;
    const int lane = tid & 31;
    const int wid = tid >> 5;
    const int wm = wid & 3;        // 4 m-warps (32 rows each)
    const int wn = wid >> 2;       // 2 n-warps (64 cols each)
    const int bx = blockIdx.x, by = blockIdx.y;

    uint32_t st_off[4];
    const char* Agp[4];
    const char* Bgp[4];
    #pragma unroll
    for (int t = 0; t < 4; t++) {
        const int idx = tid + t * 256;
        const int row = idx >> 3, c = (idx & 7) * 16;
        st_off[t] = (uint32_t)(row * 128 + (c ^ ((row & 7) * 16)));
        Agp[t] = (const char*)A + ((size_t)(by * 128 + row) * lda + (idx & 7) * 8) * 2;
        Bgp[t] = (const char*)Bm + ((size_t)(bx * 128 + row) * ldb + (idx & 7) * 8) * 2;
    }

    const uint32_t colxor = (uint32_t)((lane & 7) * 16);
    const uint32_t a_rowbase = (uint32_t)((wm * 32 + (lane & 15)) * 128);
    const uint32_t a_part = (uint32_t)((lane >> 4) * 16);
    const uint32_t b_rowbase = (uint32_t)((wn * 64 + ((lane >> 4) << 3) + (lane & 7)) * 128);
    const uint32_t b_part = (uint32_t)(((lane >> 3) & 1) * 16);

    float acc[2][8][4];
    #pragma unroll
    for (int i = 0; i < 2; i++)
        #pragma unroll
        for (int j = 0; j < 8; j++)
            #pragma unroll
            for (int u = 0; u < 4; u++) acc[i][j][u] = 0.0f;

    const int S = K2 / 64;

    #pragma unroll
    for (int p = 0; p < NBUF; p++) {
        const uint32_t ab = sbase + p * STAGE_AB;
        const uint32_t bb = ab + STAGE_BYTES;
        #pragma unroll
        for (int t = 0; t < 4; t++) {
            CPASYNC16(ab + st_off[t], Agp[t] + (size_t)p * 128);
            CPASYNC16(bb + st_off[t], Bgp[t] + (size_t)p * 128);
        }
        CPASYNC_COMMIT();
    }

    #pragma unroll 1
    for (int s = 0; s < S; s++) {
        if (s + NBUF <= S) CPASYNC_WAIT2();
        else               CPASYNC_WAIT0();
        __syncthreads();
        const uint32_t ab = sbase + (s % NBUF) * STAGE_AB;
        const uint32_t bb = ab + STAGE_BYTES;

        #pragma unroll
        for (int k = 0; k < 4; k++) {
            const uint32_t kb = (uint32_t)(k * 32);
            uint32_t a[2][4], b[8][2];
            #pragma unroll
            for (int i = 0; i < 2; i++)
                ldmatrix_x4(a[i][0], a[i][1], a[i][2], a[i][3],
                            ab + a_rowbase + (uint32_t)(i * 2048) + ((kb + a_part) ^ colxor));
            #pragma unroll
            for (int jp = 0; jp < 4; jp++) {
                uint32_t r0, r1, r2, r3;
                ldmatrix_x4(r0, r1, r2, r3,
                            bb + b_rowbase + (uint32_t)(jp * 2048) + ((kb + b_part) ^ colxor));
                b[2 * jp][0] = r0; b[2 * jp][1] = r1;
                b[2 * jp + 1][0] = r2; b[2 * jp + 1][1] = r3;
            }
            #pragma unroll
            for (int i = 0; i < 2; i++)
                #pragma unroll
                for (int j = 0; j < 8; j++)
                    mma16816(acc[i][j], a[i], b[j]);
        }
        __syncthreads();
        if (s + NBUF < S) {
            const int sn = s + NBUF;
            #pragma unroll
            for (int t = 0; t < 4; t++) {
                CPASYNC16(ab + st_off[t], Agp[t] + (size_t)sn * 128);
                CPASYNC16(bb + st_off[t], Bgp[t] + (size_t)sn * 128);
            }
            CPASYNC_COMMIT();
        }
    }

    // ---- epilogue ----
    const int row0 = by * 128 + wm * 32 + (lane >> 2);
    const int col0 = bx * 128 + wn * 64 + (lane & 3) * 2;
    #pragma unroll
    for (int j = 0; j < 8; j++) {
        const int col = col0 + j * 8;
        const float2 bv = *(const float2*)&bias[col];
        #pragma unroll
        for (int i = 0; i < 2; i++) {
            #pragma unroll
            for (int half = 0; half < 2; half++) {
                const int row = row0 + i * 16 + half * 8;
                float v0 = acc[i][j][half * 2 + 0] + bv.x;
                float v1 = acc[i][j][half * 2 + 1] + bv.y;
                if (MODE == 0) {
                    *(float2*)(C + (size_t)row * N + col) = make_float2(v0, v1);
                } else if (MODE == 2) {
                    v0 = 0.5f * v0 * (1.0f + erff(v0 * 0.70710678118654752f));
                    v1 = 0.5f * v1 * (1.0f + erff(v1 * 0.70710678118654752f));
                    *(__half2*)(C3 + (size_t)row * N + col) =
                        __halves2half2(__float2half_rn(v0), __float2half_rn(v1));
                } else {  // MODE 1: qkv split epilogue
                    const int brow = row >> 11;
                    const int srow = row & 2047;
                    const int sec = col >> 10;
                    const int within = col & 1023;
                    const int hh = within >> 6;
                    const int dd = within & 63;
                    const __half h0 = __float2half_rn(v0);
                    const __half h1 = __float2half_rn(v1);
                    if (sec == 0) {
                        *(__half2*)(q2p + (size_t)row * 1024 + hh * 64 + dd) = __halves2half2(h0, h1);
                    } else if (sec == 1) {
                        *(__half2*)(k2p + (size_t)row * 1024 + hh * 64 + dd) = __halves2half2(h0, h1);
                    } else {
                        __half* vb_ = vtp + ((size_t)(brow * Hsz + hh) * 64 + dd) * Ssz + srow;
                        *vb_ = h0;
                        *(vb_ + Ssz) = h1;
                    }
                }
            }
        }
    }
}

// ===================== FA2 flash attention (register softmax) ================
// grid (S/128, H, B), 256 threads (8 warps, each owns 16 rows x full 64 n).
// Softmax entirely in registers (quad shuffles). S-accumulator fragments are
// repacked to fp16 as the PV A-operand (no P smem). K/V double-buffered.
#define SQ2 0                    // 16KB (128 rows x 128B)
#define SK0 16384                // 2 x 8KB
#define SV0 32768                // 2 x 8KB
#define AT_SMEM 49152

__global__ __launch_bounds__(256, 2)
void flash_mma_kernel(const __half* __restrict__ q2, const __half* __restrict__ k2,
                      const __half* __restrict__ vt, __half* __restrict__ attn2)
{
    extern __shared__ __align__(1024) char sm_[];
    const uint32_t sb = smem_to_u32(sm_);

    const int tid = threadIdx.x, lane = tid & 31, w = tid >> 5;
    const int qb = blockIdx.x, h = blockIdx.y, b = blockIdx.z;
    const int NKB = Ssz / 64;   // 32

    const char* qsrc = (const char*)q2 + ((size_t)(b * Ssz + qb * 128) * 1024 + h * 64) * 2;
    const char* ksrc = (const char*)k2 + ((size_t)b * Ssz * 1024 + h * 64) * 2;
    const char* vsrc = (const char*)vt + ((size_t)(b * Hsz + h) * 64) * Ssz * 2;

    // ---- prologue fill: Q (16KB) + K(0) + V(0) ----
    #pragma unroll
    for (int it = 0; it < 4; it++) {
        const int idx = tid + it * 256;
        const int r = idx >> 3;
        const int c = (idx & 7) * 16;
        CPASYNC16(sb + SQ2 + swadr(r, 128, c), qsrc + (size_t)r * 2048 + c);
    }
    #pragma unroll
    for (int it = 0; it < 2; it++) {
        const int idx = tid + it * 256;
        const int r = idx >> 3;
        const int c = (idx & 7) * 16;
        CPASYNC16(sb + SK0 + swadr(r, 128, c), ksrc + (size_t)r * 2048 + c);
        CPASYNC16(sb + SV0 + swadr(r, 128, c), vsrc + (size_t)r * 4096 + c);
    }
    CPASYNC_COMMIT();

    const int a_row = lane & 15;
    const int a_part = (lane >> 4) * 16;
    const int b_rowo = ((lane >> 4) << 3) + (lane & 7);
    const int b_part = ((lane >> 3) & 1) * 16;

    uint32_t q[4][4];
    float o[8][4];
    #pragma unroll
    for (int j = 0; j < 8; j++)
        #pragma unroll
        for (int u = 0; u < 4; u++) o[j][u] = 0.0f;
    float m0 = -INFINITY, m1 = -INFINITY, l0 = 0.0f, l1 = 0.0f;

    #pragma unroll 1
    for (int kb = 0; kb < NKB; kb++) {
        // prefetch next K/V into alternate buffers, then wait for current
        if (kb + 1 < NKB) {
            const uint32_t ko = SK0 + ((kb + 1) & 1) * 8192;
            const uint32_t vo = SV0 + ((kb + 1) & 1) * 8192;
            #pragma unroll
            for (int it = 0; it < 2; it++) {
                const int idx = tid + it * 256;
                const int r = idx >> 3;
                const int c = (idx & 7) * 16;
                CPASYNC16(sb + ko + swadr(r, 128, c), ksrc + (size_t)((kb + 1) * 64 + r) * 2048 + c);
                CPASYNC16(sb + vo + swadr(r, 128, c), vsrc + (size_t)r * 4096 + (kb + 1) * 128 + c);
            }
            CPASYNC_COMMIT();
            CPASYNC_WAIT1();
        } else {
            CPASYNC_WAIT0();
        }
        __syncthreads();

        if (kb == 0) {
            // load Q fragments once; pre-scale by 1/8 (exact in fp16)
            const __half2 sc = __half2half2(__float2half(0.125f));
            #pragma unroll
            for (int ks = 0; ks < 4; ks++) {
                ldmatrix_x4(q[ks][0], q[ks][1], q[ks][2], q[ks][3],
                            sb + SQ2 + swadr((uint32_t)(16 * w + a_row), 128,
                                             (uint32_t)(ks * 32 + a_part)));
                #pragma unroll
                for (int u = 0; u < 4; u++) {
                    __half2 t = *(__half2*)&q[ks][u];
                    t = __hmul2(t, sc);
                    q[ks][u] = *(uint32_t*)&t;
                }
            }
        }

        const uint32_t kbuf = sb + SK0 + (kb & 1) * 8192;
        const uint32_t vbuf = sb + SV0 + (kb & 1) * 8192;

        // ---- S = Q K^T : warp tile 16(m) x 64(n tokens), 4 k-steps ----
        float s[8][4];
        #pragma unroll
        for (int j = 0; j < 8; j++)
            #pragma unroll
            for (int u = 0; u < 4; u++) s[j][u] = 0.0f;

        #pragma unroll
        for (int ks = 0; ks < 4; ks++) {
            #pragma unroll
            for (int jb = 0; jb < 4; jb++) {
                uint32_t r0, r1, r2, r3;
                ldmatrix_x4(r0, r1, r2, r3,
                            kbuf + swadr((uint32_t)(jb * 16 + b_rowo), 128,
                                         (uint32_t)(ks * 32 + b_part)));
                uint32_t bfr0[2] = {r0, r1}, bfr1[2] = {r2, r3};
                mma16816(s[2 * jb], q[ks], bfr0);
                mma16816(s[2 * jb + 1], q[ks], bfr1);
            }
        }

        // ---- register online softmax (rows r0 = lane>>2, r1 = r0+8) ----
        float vmax0 = -INFINITY, vmax1 = -INFINITY;
        #pragma unroll
        for (int j = 0; j < 8; j++) {
            vmax0 = fmaxf(vmax0, fmaxf(s[j][0], s[j][1]));
            vmax1 = fmaxf(vmax1, fmaxf(s[j][2], s[j][3]));
        }
        vmax0 = fmaxf(vmax0, __shfl_xor_sync(0xffffffffu, vmax0, 1));
        vmax0 = fmaxf(vmax0, __shfl_xor_sync(0xffffffffu, vmax0, 2));
        vmax1 = fmaxf(vmax1, __shfl_xor_sync(0xffffffffu, vmax1, 1));
        vmax1 = fmaxf(vmax1, __shfl_xor_sync(0xffffffffu, vmax1, 2));

        const float mn0 = fmaxf(m0, vmax0);
        const float mn1 = fmaxf(m1, vmax1);
        const float c0 = __expf(m0 - mn0);
        const float c1 = __expf(m1 - mn1);
        m0 = mn0; m1 = mn1;

        float rs0 = 0.0f, rs1 = 0.0f;
        #pragma unroll
        for (int j = 0; j < 8; j++) {
            s[j][0] = __expf(s[j][0] - mn0);
            s[j][1] = __expf(s[j][1] - mn0);
            s[j][2] = __expf(s[j][2] - mn1);
            s[j][3] = __expf(s[j][3] - mn1);
            rs0 += s[j][0] + s[j][1];
            rs1 += s[j][2] + s[j][3];
        }
        rs0 += __shfl_xor_sync(0xffffffffu, rs0, 1);
        rs0 += __shfl_xor_sync(0xffffffffu, rs0, 2);
        rs1 += __shfl_xor_sync(0xffffffffu, rs1, 1);
        rs1 += __shfl_xor_sync(0xffffffffu, rs1, 2);
        l0 = l0 * c0 + rs0;
        l1 = l1 * c1 + rs1;
        #pragma unroll
        for (int j = 0; j < 8; j++) {
            o[j][0] *= c0; o[j][1] *= c0;
            o[j][2] *= c1; o[j][3] *= c1;
        }

        // ---- O += P V : P fragments repacked from S accumulators ----
        #pragma unroll
        for (int ks = 0; ks < 4; ks++) {
            uint32_t a[4];
            a[0] = pkh(__float2half_rn(s[2 * ks][0]),     __float2half_rn(s[2 * ks][1]));
            a[1] = pkh(__float2half_rn(s[2 * ks][2]),     __float2half_rn(s[2 * ks][3]));
            a[2] = pkh(__float2half_rn(s[2 * ks + 1][0]), __float2half_rn(s[2 * ks + 1][1]));
            a[3] = pkh(__float2half_rn(s[2 * ks + 1][2]), __float2half_rn(s[2 * ks + 1][3]));
            #pragma unroll
            for (int jb = 0; jb < 4; jb++) {
                uint32_t r0, r1, r2, r3;
                ldmatrix_x4(r0, r1, r2, r3,
                            vbuf + swadr((uint32_t)(jb * 16 + b_rowo), 128,
                                         (uint32_t)(ks * 32 + b_part)));
                uint32_t bfr0[2] = {r0, r1}, bfr1[2] = {r2, r3};
                mma16816(o[2 * jb], a, bfr0);
                mma16816(o[2 * jb + 1], a, bfr1);
            }
        }
        __syncthreads();   // all reads of current K/V buffers done
    }

    // ---- epilogue ----
    const float inv0 = 1.0f / l0;
    const float inv1 = 1.0f / l1;
    const size_t r0g = (size_t)b * Ssz + (size_t)qb * 128 + 16 * w + (lane >> 2);
    const size_t r1g = r0g + 8;
    #pragma unroll
    for (int j = 0; j < 8; j++) {
        const int col = h * 64 + j * 8 + (lane & 3) * 2;
        *(__half2*)(attn2 + r0g * 1024 + col) = __halves2half2(
            __float2half_rn(o[j][0] * inv0), __float2half_rn(o[j][1] * inv0));
        *(__half2*)(attn2 + r1g * 1024 + col) = __halves2half2(
            __float2half_rn(o[j][2] * inv1), __float2half_rn(o[j][3] * inv1));
    }
}

// ===================== fused residual-add + LayerNorm (+fp16 out) ============
__global__ __launch_bounds__(256)
void add_ln_kernel(const float* __restrict__ A, const float* __restrict__ Bv,
                   const float* __restrict__ g, const float* __restrict__ be,
                   float* __restrict__ Y, __half* __restrict__ Y2)
{
    const int row = blockIdx.x;
    const int tid = threadIdx.x;
    const float4 av = ((const float4*)(A + (size_t)row * Esz))[tid];
    const float4 bv = ((const float4*)(Bv + (size_t)row * Esz))[tid];
    const float v0 = av.x + bv.x, v1 = av.y + bv.y, v2 = av.z + bv.z, v3 = av.w + bv.w;

    float s = v0 + v1 + v2 + v3;
    float s2 = v0 * v0 + v1 * v1 + v2 * v2 + v3 * v3;
    #pragma unroll
    for (int o = 16; o; o >>= 1) {
        s += __shfl_xor_sync(0xffffffffu, s, o);
        s2 += __shfl_xor_sync(0xffffffffu, s2, o);
    }
    __shared__ float ss[8], ss2[8];
    const int w = tid >> 5, ln = tid & 31;
    if (ln == 0) { ss[w] = s; ss2[w] = s2; }
    __syncthreads();
    if (tid < 8) {
        s = ss[tid]; s2 = ss2[tid];
        #pragma unroll
        for (int o = 4; o; o >>= 1) {
            s += __shfl_xor_sync(0x000000ffu, s, o);
            s2 += __shfl_xor_sync(0x000000ffu, s2, o);
        }
        if (tid == 0) { ss[0] = s; ss2[0] = s2; }
    }
    __syncthreads();
    const float mean = ss[0] * (1.0f / Esz);
    const float var = ss2[0] * (1.0f / Esz) - mean * mean;
    const float rstd = rsqrtf(var + 1e-5f);

    const float4 gv = ((const float4*)g)[tid];
    const float4 bev = ((const float4*)be)[tid];
    float4 o4;
    o4.x = (v0 - mean) * rstd * gv.x + bev.x;
    o4.y = (v1 - mean) * rstd * gv.y + bev.y;
    o4.z = (v2 - mean) * rstd * gv.z + bev.z;
    o4.w = (v3 - mean) * rstd * gv.w + bev.w;
    ((float4*)(Y + (size_t)row * Esz))[tid] = o4;

    if (Y2) {
        __half* base = Y2 + (size_t)row * 1024 + tid * 4;
        *(__half2*)(base) = __halves2half2(__float2half_rn(o4.x), __float2half_rn(o4.y));
        *(__half2*)(base + 2) = __halves2half2(__float2half_rn(o4.z), __float2half_rn(o4.w));
    }
}

// ===================== launch ================================================
extern "C" void kernel_launch(void* const* d_in, const int* in_sizes, int n_in,
                              void* d_out, int out_size)
{
    (void)in_sizes; (void)n_in; (void)out_size;
    const float* x     = (const float*)d_in[0];
    const float* w_qkv = (const float*)d_in[1];
    const float* b_qkv = (const float*)d_in[2];
    const float* w_out = (const float*)d_in[3];
    const float* b_out = (const float*)d_in[4];
    const float* g1    = (const float*)d_in[5];
    const float* beta1 = (const float*)d_in[6];
    const float* w_fc1 = (const float*)d_in[7];
    const float* b_fc1 = (const float*)d_in[8];
    const float* w_fc2 = (const float*)d_in[9];
    const float* b_fc2 = (const float*)d_in[10];
    const float* g2    = (const float*)d_in[11];
    const float* beta2 = (const float*)d_in[12];

    float *proj, *x1, *ff;
    cudaGetSymbolAddress((void**)&proj, g_proj);
    cudaGetSymbolAddress((void**)&x1,   g_x1);
    cudaGetSymbolAddress((void**)&ff,   g_ff);
    __half *q2, *k2, *vt, *attn2, *x2, *x12, *h2, *wq2, *wo2, *w12, *w22;
    cudaGetSymbolAddress((void**)&q2,    g_q2);
    cudaGetSymbolAddress((void**)&k2,    g_k2);
    cudaGetSymbolAddress((void**)&vt,    g_vt);
    cudaGetSymbolAddress((void**)&attn2, g_attn2);
    cudaGetSymbolAddress((void**)&x2,    g_x2);
    cudaGetSymbolAddress((void**)&x12,   g_x12);
    cudaGetSymbolAddress((void**)&h2,    g_h2);
    cudaGetSymbolAddress((void**)&wq2,   g_wqkv2);
    cudaGetSymbolAddress((void**)&wo2,   g_wout2);
    cudaGetSymbolAddress((void**)&w12,   g_wfc12);
    cudaGetSymbolAddress((void**)&w22,   g_wfc22);

    cudaFuncSetAttribute(flash_mma_kernel, cudaFuncAttributeMaxDynamicSharedMemorySize, AT_SMEM);
    cudaFuncSetAttribute(gemm_mma_kernel<0>, cudaFuncAttributeMaxDynamicSharedMemorySize, GEMM_SMEM);
    cudaFuncSetAttribute(gemm_mma_kernel<1>, cudaFuncAttributeMaxDynamicSharedMemorySize, GEMM_SMEM);
    cudaFuncSetAttribute(gemm_mma_kernel<2>, cudaFuncAttributeMaxDynamicSharedMemorySize, GEMM_SMEM);

    // 0) all fp32->fp16 converts in one kernel
    cvt_all_kernel<<<1024, 256>>>(w_qkv, w_out, w_fc1, w_fc2, x, wq2, wo2, w12, w22, x2);

    // 1) qkv = x @ w_qkv^T + b_qkv  -> q2/k2/vt
    gemm_mma_kernel<1><<<dim3(3 * Esz / 128, Msz / 128), 256, GEMM_SMEM>>>(
        x2, wq2, b_qkv, nullptr, nullptr, q2, k2, vt, 3 * Esz, Esz, Esz, Esz);
    // 2) attention -> attn2
    flash_mma_kernel<<<dim3(Ssz / 128, Hsz, Bsz), 256, AT_SMEM>>>(q2, k2, vt, attn2);
    // 3) proj = attn @ w_out^T + b_out
    gemm_mma_kernel<0><<<dim3(Esz / 128, Msz / 128), 256, GEMM_SMEM>>>(
        attn2, wo2, b_out, proj, nullptr, nullptr, nullptr, nullptr, Esz, Esz, Esz, Esz);
    // 4) x1 = LN(x + proj)  (+ x12 fp16)
    add_ln_kernel<<<Msz, 256>>>(x, proj, g1, beta1, x1, x12);
    // 5) h2 = fp16(gelu(x1 @ w_fc1^T + b_fc1))
    gemm_mma_kernel<2><<<dim3(FFsz / 128, Msz / 128), 256, GEMM_SMEM>>>(
        x12, w12, b_fc1, nullptr, h2, nullptr, nullptr, nullptr, FFsz, Esz, Esz, Esz);
    // 6) ff = h @ w_fc2^T + b_fc2
    gemm_mma_kernel<0><<<dim3(Esz / 128, Msz / 128), 256, GEMM_SMEM>>>(
        h2, w22, b_fc2, ff, nullptr, nullptr, nullptr, nullptr, Esz, FFsz, FFsz, FFsz);
    // 7) out = LN(x1 + ff)
    add_ln_kernel<<<Msz, 256>>>(x1, ff, g2, beta2, (float*)d_out, nullptr);
}